// round 9
// baseline (speedup 1.0000x reference)
#include <cuda_runtime.h>
#include <cuda_bf16.h>
#include <cuda_fp16.h>
#include <cstdint>

#define NV 100000
#define EE 1600000
#define BB 64
#define HIDDEN 128
#define DMODEL 256
#define EPSV 1e-5f
#define NBLK ((NV + 255) / 256)   // 391 scan blocks

// ---------------- scratch (static device globals; no allocation) ----------------
__device__ __half g_h16[NV * HIDDEN];   // pre-aggregation features (fp16)
__device__ __half g_x16a[NV * HIDDEN];  // activation ping (fp16)
__device__ __half g_x16b[NV * HIDDEN];  // activation pong (fp16)
__device__ float g_dinv[NV];            // deg^{-1/2}
__device__ int   g_deg[NV];             // in-degree
__device__ int   g_rowptr[NV + 1];      // CSR offsets (by dst)
__device__ int   g_pos[NV];             // running insert positions for sort
__device__ unsigned long long g_desc[NBLK];  // decoupled-lookback descriptors
__device__ int2  g_epack[EE];           // sorted edges: {src, bits(dinv[src])}
__device__ float g_summ[BB * HIDDEN];   // pooled sums
__device__ float g_cnt[BB];             // pooled counts

// ---------------- setup kernels ----------------
__global__ void zero_kernel() {
    int i = blockIdx.x * blockDim.x + threadIdx.x;
    if (i < NV) g_deg[i] = 0;
    if (i < NBLK) g_desc[i] = 0ULL;
    if (i < BB * HIDDEN) g_summ[i] = 0.f;
    if (i < BB) g_cnt[i] = 0.f;
}

__global__ void deg_kernel(const int4* __restrict__ dst4) {
    int e = blockIdx.x * blockDim.x + threadIdx.x;
    if (e < EE / 4) {
        int4 d = dst4[e];
        atomicAdd(&g_deg[d.x], 1);
        atomicAdd(&g_deg[d.y], 1);
        atomicAdd(&g_deg[d.z], 1);
        atomicAdd(&g_deg[d.w], 1);
    }
}

// --- single-pass decoupled-lookback exclusive scan of g_deg ---
// g_desc[b] = state<<32 | value.  state: 0=invalid, 1=aggregate, 2=prefix.
__global__ void scan_kernel() {
    __shared__ int s[256];
    __shared__ int sh_ex;
    int tid = threadIdx.x;
    int b = blockIdx.x;
    int i = b * 256 + tid;
    int v = (i < NV) ? g_deg[i] : 0;
    s[tid] = v;
    __syncthreads();
#pragma unroll
    for (int off = 1; off < 256; off <<= 1) {
        int t = (tid >= off) ? s[tid - off] : 0;
        __syncthreads();
        s[tid] += t;
        __syncthreads();
    }
    int incl = s[tid];
    int total = s[255];

    if (tid == 0) {
        unsigned long long ex = 0;
        if (b > 0) {
            atomicExch(&g_desc[b], (1ULL << 32) | (unsigned int)total);
            int j = b - 1;
            while (true) {
                unsigned long long d = atomicAdd(&g_desc[j], 0ULL);
                unsigned int st = (unsigned int)(d >> 32);
                if (st == 2u) { ex += (unsigned int)d; break; }
                if (st == 1u) { ex += (unsigned int)d; j--; }
            }
        }
        atomicExch(&g_desc[b], (2ULL << 32) | (unsigned int)(ex + (unsigned int)total));
        sh_ex = (int)ex;
    }
    __syncthreads();
    int excl = sh_ex + incl - v;
    if (i < NV) {
        g_rowptr[i] = excl;
        g_pos[i] = excl;
        g_dinv[i] = rsqrtf((float)v + 1.f);
    }
    if (i == NV - 1) g_rowptr[NV] = excl + v;
}

// counting-sort edges by dst; pack {src, dinv[src]} (dinv[dst] applied in agg)
__global__ void sort_kernel(const int* __restrict__ src, const int* __restrict__ dst) {
    int e = blockIdx.x * blockDim.x + threadIdx.x;
    if (e >= EE) return;
    int s = src[e], d = dst[e];
    int p = atomicAdd(&g_pos[d], 1);
    g_epack[p] = make_int2(s, __float_as_int(g_dinv[s]));
}

// ---------------- tensor-core GEMM: H16 = X @ W (bf16 split) ----------------
__device__ __forceinline__ void mma_bf16(float* c, const uint32_t* a,
                                         uint32_t b0, uint32_t b1) {
    asm volatile(
        "mma.sync.aligned.m16n8k16.row.col.f32.bf16.bf16.f32 "
        "{%0,%1,%2,%3}, {%4,%5,%6,%7}, {%8,%9}, {%0,%1,%2,%3};\n"
        : "+f"(c[0]), "+f"(c[1]), "+f"(c[2]), "+f"(c[3])
        : "r"(a[0]), "r"(a[1]), "r"(a[2]), "r"(a[3]), "r"(b0), "r"(b1));
}

#define BST 136          // smem row stride in bf16 elements
#define BSTW 68          // same, in 32-bit words
#define XTILE (128 * BST)
#define SMEM_L1 (4 * XTILE * 2 + 512 * 4)   // Xh,Xl,Wh,Wl + W_in/b_in floats
#define SMEM_L23 (3 * XTILE * 2)            // Xh,Wh,Wl

template <bool FUSE_IN, bool XLO>
__global__ void gemm_tc_kernel(const float* __restrict__ V,
                               const __half* __restrict__ X16,
                               const float* __restrict__ Wi,
                               const float* __restrict__ bi,
                               const float* __restrict__ W,
                               __half* __restrict__ H) {
    extern __shared__ __nv_bfloat16 sb[];
    __nv_bfloat16* Xh = sb;
    __nv_bfloat16* Xl = sb + XTILE;                    // only used when XLO
    __nv_bfloat16* Wh = sb + (XLO ? 2 : 1) * XTILE;
    __nv_bfloat16* Wl = sb + (XLO ? 3 : 2) * XTILE;
    float* sWin = (float*)(sb + 4 * XTILE);            // only used when FUSE_IN
    int t = threadIdx.x;
    int row0 = blockIdx.x * 128;

#pragma unroll
    for (int i = 0; i < 64; i++) {
        int idx = i * 256 + t;
        int k = idx >> 7, n = idx & 127;
        float w = W[idx];
        __nv_bfloat16 wh = __float2bfloat16_rn(w);
        float rem = w - __bfloat162float(wh);
        Wh[n * BST + k] = wh;
        Wl[n * BST + k] = __float2bfloat16_rn(rem);
    }
    if (FUSE_IN) {
        for (int i = t; i < 512; i += 256)
            sWin[i] = (i < 384) ? Wi[i] : bi[i - 384];
        __syncthreads();
    }

#pragma unroll
    for (int i = 0; i < 16; i++) {
        int idx = i * 256 + t;
        int r = idx >> 5, q = idx & 31;
        int gr = row0 + r;
        float4 v = make_float4(0.f, 0.f, 0.f, 0.f);
        if (FUSE_IN) {
            float v0 = 0.f, v1 = 0.f, v2 = 0.f;
            if (gr < NV) {
                v0 = V[gr * 3 + 0]; v1 = V[gr * 3 + 1]; v2 = V[gr * 3 + 2];
            }
            int c = q * 4;
            float* pv = &v.x;
#pragma unroll
            for (int j = 0; j < 4; j++) {
                int cc = c + j;
                pv[j] = sWin[384 + cc] + v0 * sWin[cc] + v1 * sWin[128 + cc]
                        + v2 * sWin[256 + cc];
            }
        } else if (gr < NV) {
            uint2 u = *((const uint2*)X16 + gr * 32 + q);
            float2 f0 = __half22float2(*(__half2*)&u.x);
            float2 f1 = __half22float2(*(__half2*)&u.y);
            v = make_float4(f0.x, f0.y, f1.x, f1.y);
        }
        __nv_bfloat162 h0 = __floats2bfloat162_rn(v.x, v.y);
        __nv_bfloat162 h1 = __floats2bfloat162_rn(v.z, v.w);
        int base = r * BST + q * 4;
        *(__nv_bfloat162*)(Xh + base) = h0;
        *(__nv_bfloat162*)(Xh + base + 2) = h1;
        if (XLO) {
            float2 hf0 = __bfloat1622float2(h0);
            float2 hf1 = __bfloat1622float2(h1);
            *(__nv_bfloat162*)(Xl + base) = __floats2bfloat162_rn(v.x - hf0.x, v.y - hf0.y);
            *(__nv_bfloat162*)(Xl + base + 2) = __floats2bfloat162_rn(v.z - hf1.x, v.w - hf1.y);
        }
    }
    __syncthreads();

    int w = t >> 5, lane = t & 31;
    int wr = w >> 1, wc = w & 1;
    int g = lane >> 2, q4 = lane & 3;

    float acc[2][8][4];
#pragma unroll
    for (int mt = 0; mt < 2; mt++)
#pragma unroll
        for (int nt = 0; nt < 8; nt++)
#pragma unroll
            for (int j = 0; j < 4; j++) acc[mt][nt][j] = 0.f;

    const uint32_t* pXh = (const uint32_t*)Xh;
    const uint32_t* pXl = (const uint32_t*)Xl;
    const uint32_t* pWh = (const uint32_t*)Wh;
    const uint32_t* pWl = (const uint32_t*)Wl;

#pragma unroll
    for (int ks = 0; ks < 8; ks++) {
        int kw = ks * 8 + q4;
        uint32_t ah[2][4], al[2][4];
#pragma unroll
        for (int mt = 0; mt < 2; mt++) {
            int r = wr * 32 + mt * 16 + g;
            ah[mt][0] = pXh[r * BSTW + kw];
            ah[mt][1] = pXh[(r + 8) * BSTW + kw];
            ah[mt][2] = pXh[r * BSTW + kw + 4];
            ah[mt][3] = pXh[(r + 8) * BSTW + kw + 4];
            if (XLO) {
                al[mt][0] = pXl[r * BSTW + kw];
                al[mt][1] = pXl[(r + 8) * BSTW + kw];
                al[mt][2] = pXl[r * BSTW + kw + 4];
                al[mt][3] = pXl[(r + 8) * BSTW + kw + 4];
            }
        }
#pragma unroll
        for (int nt = 0; nt < 8; nt++) {
            int n = wc * 64 + nt * 8 + g;
            uint32_t bh0 = pWh[n * BSTW + kw];
            uint32_t bh1 = pWh[n * BSTW + kw + 4];
            uint32_t bl0 = pWl[n * BSTW + kw];
            uint32_t bl1 = pWl[n * BSTW + kw + 4];
#pragma unroll
            for (int mt = 0; mt < 2; mt++) {
                mma_bf16(acc[mt][nt], ah[mt], bh0, bh1);
                mma_bf16(acc[mt][nt], ah[mt], bl0, bl1);
                if (XLO) mma_bf16(acc[mt][nt], al[mt], bh0, bh1);
            }
        }
    }

#pragma unroll
    for (int mt = 0; mt < 2; mt++) {
#pragma unroll
        for (int nt = 0; nt < 8; nt++) {
            int col = wc * 64 + nt * 8 + q4 * 2;
            int r = row0 + wr * 32 + mt * 16 + g;
            if (r < NV)
                *(__half2*)(H + r * HIDDEN + col) =
                    __floats2half2_rn(acc[mt][nt][0], acc[mt][nt][1]);
            int r2 = r + 8;
            if (r2 < NV)
                *(__half2*)(H + r2 * HIDDEN + col) =
                    __floats2half2_rn(acc[mt][nt][2], acc[mt][nt][3]);
        }
    }
}

// ---------------- aggregation core: per-row edge sum --------------------------
__device__ __forceinline__ float4 h4_to_f4(uint2 u) {
    float2 f0 = __half22float2(*(__half2*)&u.x);
    float2 f1 = __half22float2(*(__half2*)&u.y);
    return make_float4(f0.x, f0.y, f1.x, f1.y);
}

// acc = H[row]*dinv^2 + bias + dinv * sum_e dinv_s * H[src_e]   (then ReLU)
__device__ __forceinline__ float4 agg_row(const __half* __restrict__ H,
                                          const float* __restrict__ bias,
                                          int row, int lane) {
    int beg = g_rowptr[row], end = g_rowptr[row + 1];
    float dd = g_dinv[row];
    const uint2* Hp = (const uint2*)H;
    float4 es = make_float4(0.f, 0.f, 0.f, 0.f);
    int e = beg;
    for (; e + 3 < end; e += 4) {
        int2 p0 = g_epack[e];
        int2 p1 = g_epack[e + 1];
        int2 p2 = g_epack[e + 2];
        int2 p3 = g_epack[e + 3];
        float4 v0 = h4_to_f4(Hp[p0.x * 32 + lane]);
        float4 v1 = h4_to_f4(Hp[p1.x * 32 + lane]);
        float4 v2 = h4_to_f4(Hp[p2.x * 32 + lane]);
        float4 v3 = h4_to_f4(Hp[p3.x * 32 + lane]);
        float w0 = __int_as_float(p0.y);
        float w1 = __int_as_float(p1.y);
        float w2 = __int_as_float(p2.y);
        float w3 = __int_as_float(p3.y);
        es.x += w0 * v0.x + w1 * v1.x + w2 * v2.x + w3 * v3.x;
        es.y += w0 * v0.y + w1 * v1.y + w2 * v2.y + w3 * v3.y;
        es.z += w0 * v0.z + w1 * v1.z + w2 * v2.z + w3 * v3.z;
        es.w += w0 * v0.w + w1 * v1.w + w2 * v2.w + w3 * v3.w;
    }
    for (; e < end; e++) {
        int2 p = g_epack[e];
        float w = __int_as_float(p.y);
        float4 v = h4_to_f4(Hp[p.x * 32 + lane]);
        es.x += w * v.x; es.y += w * v.y;
        es.z += w * v.z; es.w += w * v.w;
    }
    float4 h = h4_to_f4(Hp[row * 32 + lane]);
    float4 b = *((const float4*)bias + lane);
    float dd2 = dd * dd;
    return make_float4(fmaxf(h.x * dd2 + b.x + dd * es.x, 0.f),
                       fmaxf(h.y * dd2 + b.y + dd * es.y, 0.f),
                       fmaxf(h.z * dd2 + b.z + dd * es.z, 0.f),
                       fmaxf(h.w * dd2 + b.w + dd * es.w, 0.f));
}

// layers 1,2: write fp16 activations
__global__ void agg_kernel(const __half* __restrict__ H,
                           const float* __restrict__ bias,
                           __half* __restrict__ OUT) {
    int row = (blockIdx.x * blockDim.x + threadIdx.x) >> 5;
    int lane = threadIdx.x & 31;
    if (row >= NV) return;
    float4 a = agg_row(H, bias, row, lane);
    uint2 o;
    *(__half2*)&o.x = __floats2half2_rn(a.x, a.y);
    *(__half2*)&o.y = __floats2half2_rn(a.z, a.w);
    *((uint2*)OUT + row * 32 + lane) = o;
}

// layer 3: fused with mean-pool accumulation (no activation write)
__global__ void agg_pool_kernel(const __half* __restrict__ H,
                                const float* __restrict__ bias,
                                const int* __restrict__ batch) {
    __shared__ float sacc[HIDDEN];
    __shared__ int scnt;
    int tid = threadIdx.x;
    int wid = tid >> 5, lane = tid & 31;
    int row = blockIdx.x * 8 + wid;          // NV = 12500*8 exactly
    if (tid < HIDDEN) sacc[tid] = 0.f;
    if (tid == 0) scnt = 0;
    __syncthreads();

    int b0 = batch[blockIdx.x * 8];
    if (row < NV) {
        float4 a = agg_row(H, bias, row, lane);
        int b = batch[row];
        if (b == b0) {
            atomicAdd(&sacc[lane * 4 + 0], a.x);
            atomicAdd(&sacc[lane * 4 + 1], a.y);
            atomicAdd(&sacc[lane * 4 + 2], a.z);
            atomicAdd(&sacc[lane * 4 + 3], a.w);
            if (lane == 0) atomicAdd(&scnt, 1);
        } else {  // rare: block straddles a batch boundary
            atomicAdd(&g_summ[b * HIDDEN + lane * 4 + 0], a.x);
            atomicAdd(&g_summ[b * HIDDEN + lane * 4 + 1], a.y);
            atomicAdd(&g_summ[b * HIDDEN + lane * 4 + 2], a.z);
            atomicAdd(&g_summ[b * HIDDEN + lane * 4 + 3], a.w);
            if (lane == 0) atomicAdd(&g_cnt[b], 1.f);
        }
    }
    __syncthreads();
    if (tid < HIDDEN) atomicAdd(&g_summ[b0 * HIDDEN + tid], sacc[tid]);
    if (tid == 0) atomicAdd(&g_cnt[b0], (float)scnt);
}

// ---------------- head: pooled @ W_out + b_out, layernorm ----------------
__global__ void final_kernel(const float* __restrict__ Wo, const float* __restrict__ bo,
                             const float* __restrict__ gamma, const float* __restrict__ beta,
                             float* __restrict__ out) {
    __shared__ float p[HIDDEN];
    __shared__ float rs[DMODEL];
    __shared__ float rq[DMODEL];
    int b = blockIdx.x, c = threadIdx.x;
    if (c < HIDDEN) {
        float cnt = fmaxf(g_cnt[b], 1.f);
        p[c] = g_summ[b * HIDDEN + c] / cnt;
    }
    __syncthreads();
    float y = bo[c];
#pragma unroll 8
    for (int k = 0; k < HIDDEN; k++) y += p[k] * Wo[k * DMODEL + c];
    rs[c] = y;
    rq[c] = y * y;
    __syncthreads();
    for (int s = DMODEL / 2; s > 0; s >>= 1) {
        if (c < s) { rs[c] += rs[c + s]; rq[c] += rq[c + s]; }
        __syncthreads();
    }
    float mu = rs[0] / (float)DMODEL;
    float var = rq[0] / (float)DMODEL - mu * mu;
    out[b * DMODEL + c] = (y - mu) * rsqrtf(var + EPSV) * gamma[c] + beta[c];
}

// ---------------- launch ----------------
extern "C" void kernel_launch(void* const* d_in, const int* in_sizes, int n_in,
                              void* d_out, int out_size) {
    const float* vertices = (const float*)d_in[0];
    const int*   eidx     = (const int*)d_in[1];
    const int*   batch    = (const int*)d_in[2];
    const float* W_in     = (const float*)d_in[3];
    const float* b_in     = (const float*)d_in[4];
    const float* W1       = (const float*)d_in[5];
    const float* b1       = (const float*)d_in[6];
    const float* W2       = (const float*)d_in[7];
    const float* b2       = (const float*)d_in[8];
    const float* W3       = (const float*)d_in[9];
    const float* b3       = (const float*)d_in[10];
    const float* W_out    = (const float*)d_in[11];
    const float* b_out    = (const float*)d_in[12];
    const float* gamma    = (const float*)d_in[13];
    const float* beta     = (const float*)d_in[14];
    const int* src = eidx;
    const int* dst = eidx + EE;
    float* out = (float*)d_out;

    __half *ph, *pxa, *pxb;
    cudaGetSymbolAddress((void**)&ph, g_h16);
    cudaGetSymbolAddress((void**)&pxa, g_x16a);
    cudaGetSymbolAddress((void**)&pxb, g_x16b);

    cudaFuncSetAttribute((gemm_tc_kernel<true, true>),
                         cudaFuncAttributeMaxDynamicSharedMemorySize, SMEM_L1);
    cudaFuncSetAttribute((gemm_tc_kernel<false, false>),
                         cudaFuncAttributeMaxDynamicSharedMemorySize, SMEM_L23);

    int nb256 = (NV + 255) / 256;
    zero_kernel<<<nb256, 256>>>();
    deg_kernel<<<(EE / 4 + 255) / 256, 256>>>((const int4*)dst);
    scan_kernel<<<NBLK, 256>>>();
    sort_kernel<<<(EE + 255) / 256, 256>>>(src, dst);

    int gblocks = (NV + 127) / 128;
    int ablocks = (int)(((long long)NV * 32 + 255) / 256);

    // layer 1: input projection fused into GEMM (fp32 X -> full hi/lo split)
    gemm_tc_kernel<true, true><<<gblocks, 256, SMEM_L1>>>(vertices, (const __half*)0,
                                                          W_in, b_in, W1, ph);
    agg_kernel<<<ablocks, 256>>>(ph, b1, pxa);

    // layers 2,3: fp16 X -> hi-only (2 MMAs)
    gemm_tc_kernel<false, false><<<gblocks, 256, SMEM_L23>>>((const float*)0, pxa,
                                                             (const float*)0, (const float*)0, W2, ph);
    agg_kernel<<<ablocks, 256>>>(ph, b2, pxb);

    gemm_tc_kernel<false, false><<<gblocks, 256, SMEM_L23>>>((const float*)0, pxb,
                                                             (const float*)0, (const float*)0, W3, ph);
    agg_pool_kernel<<<NV / 8, 256>>>(ph, b3, batch);

    final_kernel<<<BB, DMODEL>>>(W_out, b_out, gamma, beta, out);
}

// round 10
// speedup vs baseline: 1.0636x; 1.0636x over previous
#include <cuda_runtime.h>
#include <cuda_bf16.h>
#include <cuda_fp16.h>
#include <cstdint>

#define NV 100000
#define EE 1600000
#define BB 64
#define HIDDEN 128
#define DMODEL 256
#define EPSV 1e-5f
#define POOL_ROWS 128
#define NBLK ((NV + 255) / 256)   // 391 scan blocks

// ---------------- scratch (static device globals; no allocation) ----------------
__device__ __half g_h16[NV * HIDDEN];   // dinv-scaled pre-agg features H' (fp16)
__device__ __half g_x16a[NV * HIDDEN];  // activation ping (fp16)
__device__ __half g_x16b[NV * HIDDEN];  // activation pong (fp16)
__device__ float g_dinv[NV];            // deg^{-1/2}
__device__ int   g_deg[NV];             // in-degree
__device__ int   g_rowptr[NV + 1];      // CSR offsets (by dst)
__device__ int   g_pos[NV];             // running insert positions for sort
__device__ unsigned long long g_desc[NBLK];  // decoupled-lookback descriptors
__device__ int   g_esrc[EE];            // sorted edges: src only (dinv folded into H')
__device__ float g_summ[BB * HIDDEN];   // pooled sums
__device__ float g_cnt[BB];             // pooled counts

// ---------------- setup kernels ----------------
__global__ void zero_kernel() {
    int i = blockIdx.x * blockDim.x + threadIdx.x;
    if (i < NV) g_deg[i] = 0;
    if (i < NBLK) g_desc[i] = 0ULL;
    if (i < BB * HIDDEN) g_summ[i] = 0.f;
    if (i < BB) g_cnt[i] = 0.f;
}

__global__ void deg_kernel(const int4* __restrict__ dst4) {
    int e = blockIdx.x * blockDim.x + threadIdx.x;
    if (e < EE / 4) {
        int4 d = dst4[e];
        atomicAdd(&g_deg[d.x], 1);
        atomicAdd(&g_deg[d.y], 1);
        atomicAdd(&g_deg[d.z], 1);
        atomicAdd(&g_deg[d.w], 1);
    }
}

// --- single-pass decoupled-lookback exclusive scan of g_deg ---
__global__ void scan_kernel() {
    __shared__ int s[256];
    __shared__ int sh_ex;
    int tid = threadIdx.x;
    int b = blockIdx.x;
    int i = b * 256 + tid;
    int v = (i < NV) ? g_deg[i] : 0;
    s[tid] = v;
    __syncthreads();
#pragma unroll
    for (int off = 1; off < 256; off <<= 1) {
        int t = (tid >= off) ? s[tid - off] : 0;
        __syncthreads();
        s[tid] += t;
        __syncthreads();
    }
    int incl = s[tid];
    int total = s[255];

    if (tid == 0) {
        unsigned long long ex = 0;
        if (b > 0) {
            atomicExch(&g_desc[b], (1ULL << 32) | (unsigned int)total);
            int j = b - 1;
            while (true) {
                unsigned long long d = atomicAdd(&g_desc[j], 0ULL);
                unsigned int st = (unsigned int)(d >> 32);
                if (st == 2u) { ex += (unsigned int)d; break; }
                if (st == 1u) { ex += (unsigned int)d; j--; }
            }
        }
        atomicExch(&g_desc[b], (2ULL << 32) | (unsigned int)(ex + (unsigned int)total));
        sh_ex = (int)ex;
    }
    __syncthreads();
    int excl = sh_ex + incl - v;
    if (i < NV) {
        g_rowptr[i] = excl;
        g_pos[i] = excl;
        g_dinv[i] = rsqrtf((float)v + 1.f);
    }
    if (i == NV - 1) g_rowptr[NV] = excl + v;
}

// counting-sort edges by dst; store src only (4B scatter, no gathers)
__global__ void sort_kernel(const int* __restrict__ src, const int* __restrict__ dst) {
    int e = blockIdx.x * blockDim.x + threadIdx.x;
    if (e >= EE) return;
    int d = dst[e];
    int p = atomicAdd(&g_pos[d], 1);
    g_esrc[p] = src[e];
}

// ---------------- tensor-core GEMM: H' = dinv * (X @ W)  (bf16 split) ----------
__device__ __forceinline__ void mma_bf16(float* c, const uint32_t* a,
                                         uint32_t b0, uint32_t b1) {
    asm volatile(
        "mma.sync.aligned.m16n8k16.row.col.f32.bf16.bf16.f32 "
        "{%0,%1,%2,%3}, {%4,%5,%6,%7}, {%8,%9}, {%0,%1,%2,%3};\n"
        : "+f"(c[0]), "+f"(c[1]), "+f"(c[2]), "+f"(c[3])
        : "r"(a[0]), "r"(a[1]), "r"(a[2]), "r"(a[3]), "r"(b0), "r"(b1));
}

#define BST 136          // smem row stride in bf16 elements
#define BSTW 68          // same, in 32-bit words
#define XTILE (128 * BST)
#define SMEM_L1 (4 * XTILE * 2 + 512 * 4)   // Xh,Xl,Wh,Wl + W_in/b_in floats
#define SMEM_L23 (3 * XTILE * 2)            // Xh,Wh,Wl

template <bool FUSE_IN, bool XLO>
__global__ void gemm_tc_kernel(const float* __restrict__ V,
                               const __half* __restrict__ X16,
                               const float* __restrict__ Wi,
                               const float* __restrict__ bi,
                               const float* __restrict__ W,
                               __half* __restrict__ H) {
    extern __shared__ __nv_bfloat16 sb[];
    __nv_bfloat16* Xh = sb;
    __nv_bfloat16* Xl = sb + XTILE;                    // only used when XLO
    __nv_bfloat16* Wh = sb + (XLO ? 2 : 1) * XTILE;
    __nv_bfloat16* Wl = sb + (XLO ? 3 : 2) * XTILE;
    float* sWin = (float*)(sb + 4 * XTILE);            // only used when FUSE_IN
    int t = threadIdx.x;
    int row0 = blockIdx.x * 128;

#pragma unroll
    for (int i = 0; i < 64; i++) {
        int idx = i * 256 + t;
        int k = idx >> 7, n = idx & 127;
        float w = W[idx];
        __nv_bfloat16 wh = __float2bfloat16_rn(w);
        float rem = w - __bfloat162float(wh);
        Wh[n * BST + k] = wh;
        Wl[n * BST + k] = __float2bfloat16_rn(rem);
    }
    if (FUSE_IN) {
        for (int i = t; i < 512; i += 256)
            sWin[i] = (i < 384) ? Wi[i] : bi[i - 384];
        __syncthreads();
    }

#pragma unroll
    for (int i = 0; i < 16; i++) {
        int idx = i * 256 + t;
        int r = idx >> 5, q = idx & 31;
        int gr = row0 + r;
        float4 v = make_float4(0.f, 0.f, 0.f, 0.f);
        if (FUSE_IN) {
            float v0 = 0.f, v1 = 0.f, v2 = 0.f;
            if (gr < NV) {
                v0 = V[gr * 3 + 0]; v1 = V[gr * 3 + 1]; v2 = V[gr * 3 + 2];
            }
            int c = q * 4;
            float* pv = &v.x;
#pragma unroll
            for (int j = 0; j < 4; j++) {
                int cc = c + j;
                pv[j] = sWin[384 + cc] + v0 * sWin[cc] + v1 * sWin[128 + cc]
                        + v2 * sWin[256 + cc];
            }
        } else if (gr < NV) {
            uint2 u = *((const uint2*)X16 + gr * 32 + q);
            float2 f0 = __half22float2(*(__half2*)&u.x);
            float2 f1 = __half22float2(*(__half2*)&u.y);
            v = make_float4(f0.x, f0.y, f1.x, f1.y);
        }
        __nv_bfloat162 h0 = __floats2bfloat162_rn(v.x, v.y);
        __nv_bfloat162 h1 = __floats2bfloat162_rn(v.z, v.w);
        int base = r * BST + q * 4;
        *(__nv_bfloat162*)(Xh + base) = h0;
        *(__nv_bfloat162*)(Xh + base + 2) = h1;
        if (XLO) {
            float2 hf0 = __bfloat1622float2(h0);
            float2 hf1 = __bfloat1622float2(h1);
            *(__nv_bfloat162*)(Xl + base) = __floats2bfloat162_rn(v.x - hf0.x, v.y - hf0.y);
            *(__nv_bfloat162*)(Xl + base + 2) = __floats2bfloat162_rn(v.z - hf1.x, v.w - hf1.y);
        }
    }
    __syncthreads();

    int w = t >> 5, lane = t & 31;
    int wr = w >> 1, wc = w & 1;
    int g = lane >> 2, q4 = lane & 3;

    float acc[2][8][4];
#pragma unroll
    for (int mt = 0; mt < 2; mt++)
#pragma unroll
        for (int nt = 0; nt < 8; nt++)
#pragma unroll
            for (int j = 0; j < 4; j++) acc[mt][nt][j] = 0.f;

    const uint32_t* pXh = (const uint32_t*)Xh;
    const uint32_t* pXl = (const uint32_t*)Xl;
    const uint32_t* pWh = (const uint32_t*)Wh;
    const uint32_t* pWl = (const uint32_t*)Wl;

#pragma unroll
    for (int ks = 0; ks < 8; ks++) {
        int kw = ks * 8 + q4;
        uint32_t ah[2][4], al[2][4];
#pragma unroll
        for (int mt = 0; mt < 2; mt++) {
            int r = wr * 32 + mt * 16 + g;
            ah[mt][0] = pXh[r * BSTW + kw];
            ah[mt][1] = pXh[(r + 8) * BSTW + kw];
            ah[mt][2] = pXh[r * BSTW + kw + 4];
            ah[mt][3] = pXh[(r + 8) * BSTW + kw + 4];
            if (XLO) {
                al[mt][0] = pXl[r * BSTW + kw];
                al[mt][1] = pXl[(r + 8) * BSTW + kw];
                al[mt][2] = pXl[r * BSTW + kw + 4];
                al[mt][3] = pXl[(r + 8) * BSTW + kw + 4];
            }
        }
#pragma unroll
        for (int nt = 0; nt < 8; nt++) {
            int n = wc * 64 + nt * 8 + g;
            uint32_t bh0 = pWh[n * BSTW + kw];
            uint32_t bh1 = pWh[n * BSTW + kw + 4];
            uint32_t bl0 = pWl[n * BSTW + kw];
            uint32_t bl1 = pWl[n * BSTW + kw + 4];
#pragma unroll
            for (int mt = 0; mt < 2; mt++) {
                mma_bf16(acc[mt][nt], ah[mt], bh0, bh1);
                mma_bf16(acc[mt][nt], ah[mt], bl0, bl1);
                if (XLO) mma_bf16(acc[mt][nt], al[mt], bh0, bh1);
            }
        }
    }

    // epilogue: scale by dinv[row], store fp16 H'
#pragma unroll
    for (int mt = 0; mt < 2; mt++) {
        int rbase = row0 + wr * 32 + mt * 16 + g;
        float d0 = (rbase < NV) ? g_dinv[rbase] : 0.f;
        float d1 = (rbase + 8 < NV) ? g_dinv[rbase + 8] : 0.f;
#pragma unroll
        for (int nt = 0; nt < 8; nt++) {
            int col = wc * 64 + nt * 8 + q4 * 2;
            if (rbase < NV)
                *(__half2*)(H + rbase * HIDDEN + col) =
                    __floats2half2_rn(acc[mt][nt][0] * d0, acc[mt][nt][1] * d0);
            if (rbase + 8 < NV)
                *(__half2*)(H + (rbase + 8) * HIDDEN + col) =
                    __floats2half2_rn(acc[mt][nt][2] * d1, acc[mt][nt][3] * d1);
        }
    }
}

// ---------------- aggregation: one warp per dst row ---------------------------
__device__ __forceinline__ float4 h4_to_f4(uint2 u) {
    float2 f0 = __half22float2(*(__half2*)&u.x);
    float2 f1 = __half22float2(*(__half2*)&u.y);
    return make_float4(f0.x, f0.y, f1.x, f1.y);
}

// OUT[row] = ReLU( dd * ( H'[row] + sum_e H'[src_e] ) + bias ),  dd = dinv[row]
// (H' already carries one dinv factor per its own row.)
__global__ void agg_kernel(const __half* __restrict__ H,
                           const float* __restrict__ bias,
                           __half* __restrict__ OUT) {
    int row = (blockIdx.x * blockDim.x + threadIdx.x) >> 5;
    int lane = threadIdx.x & 31;
    if (row >= NV) return;
    int beg = g_rowptr[row], end = g_rowptr[row + 1];
    float dd = g_dinv[row];
    const uint2* Hp = (const uint2*)H;
    float4 es = make_float4(0.f, 0.f, 0.f, 0.f);
    int e = beg;
    for (; e + 3 < end; e += 4) {
        int s0 = g_esrc[e];
        int s1 = g_esrc[e + 1];
        int s2 = g_esrc[e + 2];
        int s3 = g_esrc[e + 3];
        float4 v0 = h4_to_f4(Hp[s0 * 32 + lane]);
        float4 v1 = h4_to_f4(Hp[s1 * 32 + lane]);
        float4 v2 = h4_to_f4(Hp[s2 * 32 + lane]);
        float4 v3 = h4_to_f4(Hp[s3 * 32 + lane]);
        es.x += (v0.x + v1.x) + (v2.x + v3.x);
        es.y += (v0.y + v1.y) + (v2.y + v3.y);
        es.z += (v0.z + v1.z) + (v2.z + v3.z);
        es.w += (v0.w + v1.w) + (v2.w + v3.w);
    }
    for (; e < end; e++) {
        float4 v = h4_to_f4(Hp[g_esrc[e] * 32 + lane]);
        es.x += v.x; es.y += v.y; es.z += v.z; es.w += v.w;
    }
    float4 h = h4_to_f4(Hp[row * 32 + lane]);
    float4 b = *((const float4*)bias + lane);
    uint2 o;
    *(__half2*)&o.x = __floats2half2_rn(fmaxf((h.x + es.x) * dd + b.x, 0.f),
                                        fmaxf((h.y + es.y) * dd + b.y, 0.f));
    *(__half2*)&o.y = __floats2half2_rn(fmaxf((h.z + es.z) * dd + b.z, 0.f),
                                        fmaxf((h.w + es.w) * dd + b.w, 0.f));
    *((uint2*)OUT + row * 32 + lane) = o;
}

// ---------------- pooling over sorted batch (fp16 in, already ReLU'd) ----------
__global__ void pool_kernel(const __half* __restrict__ X, const int* __restrict__ batch) {
    int c = threadIdx.x;
    int row0 = blockIdx.x * POOL_ROWS;
    if (row0 >= NV) return;
    int rend = min(row0 + POOL_ROWS, NV);
    float acc = 0.f;
    int cur = batch[row0];
    int runstart = row0;
    for (int r = row0; r < rend; r++) {
        int b = batch[r];
        if (b != cur) {
            atomicAdd(&g_summ[cur * HIDDEN + c], acc);
            if (c == 0) atomicAdd(&g_cnt[cur], (float)(r - runstart));
            acc = 0.f; cur = b; runstart = r;
        }
        acc += __half2float(X[(long long)r * HIDDEN + c]);
    }
    atomicAdd(&g_summ[cur * HIDDEN + c], acc);
    if (c == 0) atomicAdd(&g_cnt[cur], (float)(rend - runstart));
}

// ---------------- head: pooled @ W_out + b_out, layernorm ----------------
__global__ void final_kernel(const float* __restrict__ Wo, const float* __restrict__ bo,
                             const float* __restrict__ gamma, const float* __restrict__ beta,
                             float* __restrict__ out) {
    __shared__ float p[HIDDEN];
    __shared__ float rs[DMODEL];
    __shared__ float rq[DMODEL];
    int b = blockIdx.x, c = threadIdx.x;
    if (c < HIDDEN) {
        float cnt = fmaxf(g_cnt[b], 1.f);
        p[c] = g_summ[b * HIDDEN + c] / cnt;
    }
    __syncthreads();
    float y = bo[c];
#pragma unroll 8
    for (int k = 0; k < HIDDEN; k++) y += p[k] * Wo[k * DMODEL + c];
    rs[c] = y;
    rq[c] = y * y;
    __syncthreads();
    for (int s = DMODEL / 2; s > 0; s >>= 1) {
        if (c < s) { rs[c] += rs[c + s]; rq[c] += rq[c + s]; }
        __syncthreads();
    }
    float mu = rs[0] / (float)DMODEL;
    float var = rq[0] / (float)DMODEL - mu * mu;
    out[b * DMODEL + c] = (y - mu) * rsqrtf(var + EPSV) * gamma[c] + beta[c];
}

// ---------------- launch ----------------
extern "C" void kernel_launch(void* const* d_in, const int* in_sizes, int n_in,
                              void* d_out, int out_size) {
    const float* vertices = (const float*)d_in[0];
    const int*   eidx     = (const int*)d_in[1];
    const int*   batch    = (const int*)d_in[2];
    const float* W_in     = (const float*)d_in[3];
    const float* b_in     = (const float*)d_in[4];
    const float* W1       = (const float*)d_in[5];
    const float* b1       = (const float*)d_in[6];
    const float* W2       = (const float*)d_in[7];
    const float* b2       = (const float*)d_in[8];
    const float* W3       = (const float*)d_in[9];
    const float* b3       = (const float*)d_in[10];
    const float* W_out    = (const float*)d_in[11];
    const float* b_out    = (const float*)d_in[12];
    const float* gamma    = (const float*)d_in[13];
    const float* beta     = (const float*)d_in[14];
    const int* src = eidx;
    const int* dst = eidx + EE;
    float* out = (float*)d_out;

    __half *ph, *pxa, *pxb;
    cudaGetSymbolAddress((void**)&ph, g_h16);
    cudaGetSymbolAddress((void**)&pxa, g_x16a);
    cudaGetSymbolAddress((void**)&pxb, g_x16b);

    cudaFuncSetAttribute((gemm_tc_kernel<true, true>),
                         cudaFuncAttributeMaxDynamicSharedMemorySize, SMEM_L1);
    cudaFuncSetAttribute((gemm_tc_kernel<false, false>),
                         cudaFuncAttributeMaxDynamicSharedMemorySize, SMEM_L23);

    int nb256 = (NV + 255) / 256;
    zero_kernel<<<nb256, 256>>>();
    deg_kernel<<<(EE / 4 + 255) / 256, 256>>>((const int4*)dst);
    scan_kernel<<<NBLK, 256>>>();
    sort_kernel<<<(EE + 255) / 256, 256>>>(src, dst);

    int gblocks = (NV + 127) / 128;
    int ablocks = (int)(((long long)NV * 32 + 255) / 256);

    // layer 1: input projection fused into GEMM (fp32 X -> full hi/lo split)
    gemm_tc_kernel<true, true><<<gblocks, 256, SMEM_L1>>>(vertices, (const __half*)0,
                                                          W_in, b_in, W1, ph);
    agg_kernel<<<ablocks, 256>>>(ph, b1, pxa);

    // layers 2,3: fp16 X -> hi-only (2 MMAs)
    gemm_tc_kernel<false, false><<<gblocks, 256, SMEM_L23>>>((const float*)0, pxa,
                                                             (const float*)0, (const float*)0, W2, ph);
    agg_kernel<<<ablocks, 256>>>(ph, b2, pxb);

    gemm_tc_kernel<false, false><<<gblocks, 256, SMEM_L23>>>((const float*)0, pxb,
                                                             (const float*)0, (const float*)0, W3, ph);
    agg_kernel<<<ablocks, 256>>>(ph, b3, pxa);

    pool_kernel<<<(NV + POOL_ROWS - 1) / POOL_ROWS, POOL_ROWS>>>(pxa, batch);
    final_kernel<<<BB, DMODEL>>>(W_out, b_out, gamma, beta, out);
}

// round 12
// speedup vs baseline: 1.1646x; 1.0949x over previous
#include <cuda_runtime.h>
#include <cuda_bf16.h>
#include <cuda_fp16.h>
#include <cstdint>

#define NV 100000
#define EE 1600000
#define BB 64
#define HIDDEN 128
#define DMODEL 256
#define EPSV 1e-5f
#define POOL_ROWS 128
#define NBLK ((NV + 255) / 256)   // 391 scan blocks

// ---------------- scratch (static device globals; no allocation) ----------------
// NOTE: g_deg, g_desc, g_summ, g_cnt rely on the self-cleaning invariant:
// zero at module load, re-zeroed by final_kernel's tail every call.
__device__ __half g_h16[NV * HIDDEN];   // dinv-scaled pre-agg features H' (fp16)
__device__ __half g_x16a[NV * HIDDEN];  // activation ping (fp16)
__device__ __half g_x16b[NV * HIDDEN];  // activation pong (fp16)
__device__ float g_dinv[NV];            // deg^{-1/2}
__device__ int   g_deg[NV];             // in-degree
__device__ int   g_rowptr[NV + 1];      // CSR offsets (by dst)
__device__ int   g_pos[NV];             // running insert positions for sort
__device__ unsigned long long g_desc[NBLK];  // decoupled-lookback descriptors
__device__ int   g_esrc[EE];            // sorted edges: src only (dinv folded into H')
__device__ float g_summ[BB * HIDDEN];   // pooled sums
__device__ float g_cnt[BB];             // pooled counts
__device__ __nv_bfloat16 g_wh[3][HIDDEN * HIDDEN];  // pre-split W, transposed [n][k]
__device__ __nv_bfloat16 g_wl[3][HIDDEN * HIDDEN];

// ---------------- setup kernels ----------------
__global__ void deg_kernel(const int4* __restrict__ dst4) {
    int e = blockIdx.x * blockDim.x + threadIdx.x;
    if (e < EE / 4) {
        int4 d = dst4[e];
        atomicAdd(&g_deg[d.x], 1);
        atomicAdd(&g_deg[d.y], 1);
        atomicAdd(&g_deg[d.z], 1);
        atomicAdd(&g_deg[d.w], 1);
    }
}

// pre-split the three layer weights into bf16 hi/lo, transposed [n][k] packed
__global__ void wsplit_kernel(const float* __restrict__ W1,
                              const float* __restrict__ W2,
                              const float* __restrict__ W3) {
    int i = blockIdx.x * blockDim.x + threadIdx.x;   // 0 .. 3*16384-1
    if (i >= 3 * HIDDEN * HIDDEN) return;
    int l = i >> 14, idx = i & 16383;
    const float* W = (l == 0) ? W1 : (l == 1) ? W2 : W3;
    int k = idx >> 7, n = idx & 127;
    float w = W[idx];
    __nv_bfloat16 wh = __float2bfloat16_rn(w);
    g_wh[l][n * HIDDEN + k] = wh;
    g_wl[l][n * HIDDEN + k] = __float2bfloat16_rn(w - __bfloat162float(wh));
}

// --- single-pass decoupled-lookback exclusive scan of g_deg ---
__global__ void scan_kernel() {
    __shared__ int s[256];
    __shared__ int sh_ex;
    int tid = threadIdx.x;
    int b = blockIdx.x;
    int i = b * 256 + tid;
    int v = (i < NV) ? g_deg[i] : 0;
    s[tid] = v;
    __syncthreads();
#pragma unroll
    for (int off = 1; off < 256; off <<= 1) {
        int t = (tid >= off) ? s[tid - off] : 0;
        __syncthreads();
        s[tid] += t;
        __syncthreads();
    }
    int incl = s[tid];
    int total = s[255];

    if (tid == 0) {
        unsigned long long ex = 0;
        if (b > 0) {
            atomicExch(&g_desc[b], (1ULL << 32) | (unsigned int)total);
            int j = b - 1;
            while (true) {
                unsigned long long d = atomicAdd(&g_desc[j], 0ULL);
                unsigned int st = (unsigned int)(d >> 32);
                if (st == 2u) { ex += (unsigned int)d; break; }
                if (st == 1u) { ex += (unsigned int)d; j--; }
            }
        }
        atomicExch(&g_desc[b], (2ULL << 32) | (unsigned int)(ex + (unsigned int)total));
        sh_ex = (int)ex;
    }
    __syncthreads();
    int excl = sh_ex + incl - v;
    if (i < NV) {
        g_rowptr[i] = excl;
        g_pos[i] = excl;
        g_dinv[i] = rsqrtf((float)v + 1.f);
    }
    if (i == NV - 1) g_rowptr[NV] = excl + v;
}

// counting-sort edges by dst; 4 edges per thread for MLP on the atomic chain
__global__ void sort_kernel(const int4* __restrict__ src4, const int4* __restrict__ dst4) {
    int e = blockIdx.x * blockDim.x + threadIdx.x;
    if (e >= EE / 4) return;
    int4 d = dst4[e];
    int4 s = src4[e];
    int p0 = atomicAdd(&g_pos[d.x], 1);
    int p1 = atomicAdd(&g_pos[d.y], 1);
    int p2 = atomicAdd(&g_pos[d.z], 1);
    int p3 = atomicAdd(&g_pos[d.w], 1);
    g_esrc[p0] = s.x;
    g_esrc[p1] = s.y;
    g_esrc[p2] = s.z;
    g_esrc[p3] = s.w;
}

// ---------------- tensor-core GEMM: H' = dinv * (X @ W)  (bf16 split) ----------
__device__ __forceinline__ void mma_bf16(float* c, const uint32_t* a,
                                         uint32_t b0, uint32_t b1) {
    asm volatile(
        "mma.sync.aligned.m16n8k16.row.col.f32.bf16.bf16.f32 "
        "{%0,%1,%2,%3}, {%4,%5,%6,%7}, {%8,%9}, {%0,%1,%2,%3};\n"
        : "+f"(c[0]), "+f"(c[1]), "+f"(c[2]), "+f"(c[3])
        : "r"(a[0]), "r"(a[1]), "r"(a[2]), "r"(a[3]), "r"(b0), "r"(b1));
}

#define BST 136          // smem row stride in bf16 elements
#define BSTW 68          // same, in 32-bit words
#define XTILE (128 * BST)
#define SMEM_L1 (4 * XTILE * 2 + 512 * 4)   // Xh,Xl,Wh,Wl + W_in/b_in floats
#define SMEM_L23 (3 * XTILE * 2)            // Xh,Wh,Wl

template <bool FUSE_IN, bool XLO>
__global__ void gemm_tc_kernel(const float* __restrict__ V,
                               const __half* __restrict__ X16,
                               const float* __restrict__ Wi,
                               const float* __restrict__ bi,
                               const __nv_bfloat16* __restrict__ Whg,
                               const __nv_bfloat16* __restrict__ Wlg,
                               __half* __restrict__ H) {
    extern __shared__ __nv_bfloat16 sb[];
    __nv_bfloat16* Xh = sb;
    __nv_bfloat16* Xl = sb + XTILE;                    // only used when XLO
    __nv_bfloat16* Wh = sb + (XLO ? 2 : 1) * XTILE;
    __nv_bfloat16* Wl = sb + (XLO ? 3 : 2) * XTILE;
    float* sWin = (float*)(sb + 4 * XTILE);            // only used when FUSE_IN
    int t = threadIdx.x;
    int row0 = blockIdx.x * 128;

    // pre-split W (bf16, packed [n][k]) -> padded smem via float4 copies
#pragma unroll
    for (int i = 0; i < 8; i++) {
        int w4 = i * 256 + t;                // float4 slot 0..2047
        int n = w4 >> 4, kq = w4 & 15;       // 16 float4 per 128-half row
        *(float4*)(Wh + n * BST + kq * 8) = *((const float4*)Whg + w4);
        *(float4*)(Wl + n * BST + kq * 8) = *((const float4*)Wlg + w4);
    }
    if (FUSE_IN) {
        for (int i = t; i < 512; i += 256)
            sWin[i] = (i < 384) ? Wi[i] : bi[i - 384];
        __syncthreads();
    }

#pragma unroll
    for (int i = 0; i < 16; i++) {
        int idx = i * 256 + t;
        int r = idx >> 5, q = idx & 31;
        int gr = row0 + r;
        float4 v = make_float4(0.f, 0.f, 0.f, 0.f);
        if (FUSE_IN) {
            float v0 = 0.f, v1 = 0.f, v2 = 0.f;
            if (gr < NV) {
                v0 = V[gr * 3 + 0]; v1 = V[gr * 3 + 1]; v2 = V[gr * 3 + 2];
            }
            int c = q * 4;
            float* pv = &v.x;
#pragma unroll
            for (int j = 0; j < 4; j++) {
                int cc = c + j;
                pv[j] = sWin[384 + cc] + v0 * sWin[cc] + v1 * sWin[128 + cc]
                        + v2 * sWin[256 + cc];
            }
        } else if (gr < NV) {
            uint2 u = *((const uint2*)X16 + gr * 32 + q);
            float2 f0 = __half22float2(*(__half2*)&u.x);
            float2 f1 = __half22float2(*(__half2*)&u.y);
            v = make_float4(f0.x, f0.y, f1.x, f1.y);
        }
        __nv_bfloat162 h0 = __floats2bfloat162_rn(v.x, v.y);
        __nv_bfloat162 h1 = __floats2bfloat162_rn(v.z, v.w);
        int base = r * BST + q * 4;
        *(__nv_bfloat162*)(Xh + base) = h0;
        *(__nv_bfloat162*)(Xh + base + 2) = h1;
        if (XLO) {
            float2 hf0 = __bfloat1622float2(h0);
            float2 hf1 = __bfloat1622float2(h1);
            *(__nv_bfloat162*)(Xl + base) = __floats2bfloat162_rn(v.x - hf0.x, v.y - hf0.y);
            *(__nv_bfloat162*)(Xl + base + 2) = __floats2bfloat162_rn(v.z - hf1.x, v.w - hf1.y);
        }
    }
    __syncthreads();

    int w = t >> 5, lane = t & 31;
    int wr = w >> 1, wc = w & 1;
    int g = lane >> 2, q4 = lane & 3;

    float acc[2][8][4];
#pragma unroll
    for (int mt = 0; mt < 2; mt++)
#pragma unroll
        for (int nt = 0; nt < 8; nt++)
#pragma unroll
            for (int j = 0; j < 4; j++) acc[mt][nt][j] = 0.f;

    const uint32_t* pXh = (const uint32_t*)Xh;
    const uint32_t* pXl = (const uint32_t*)Xl;
    const uint32_t* pWh = (const uint32_t*)Wh;
    const uint32_t* pWl = (const uint32_t*)Wl;

#pragma unroll
    for (int ks = 0; ks < 8; ks++) {
        int kw = ks * 8 + q4;
        uint32_t ah[2][4], al[2][4];
#pragma unroll
        for (int mt = 0; mt < 2; mt++) {
            int r = wr * 32 + mt * 16 + g;
            ah[mt][0] = pXh[r * BSTW + kw];
            ah[mt][1] = pXh[(r + 8) * BSTW + kw];
            ah[mt][2] = pXh[r * BSTW + kw + 4];
            ah[mt][3] = pXh[(r + 8) * BSTW + kw + 4];
            if (XLO) {
                al[mt][0] = pXl[r * BSTW + kw];
                al[mt][1] = pXl[(r + 8) * BSTW + kw];
                al[mt][2] = pXl[r * BSTW + kw + 4];
                al[mt][3] = pXl[(r + 8) * BSTW + kw + 4];
            }
        }
#pragma unroll
        for (int nt = 0; nt < 8; nt++) {
            int n = wc * 64 + nt * 8 + g;
            uint32_t bh0 = pWh[n * BSTW + kw];
            uint32_t bh1 = pWh[n * BSTW + kw + 4];
            uint32_t bl0 = pWl[n * BSTW + kw];
            uint32_t bl1 = pWl[n * BSTW + kw + 4];
#pragma unroll
            for (int mt = 0; mt < 2; mt++) {
                mma_bf16(acc[mt][nt], ah[mt], bh0, bh1);
                mma_bf16(acc[mt][nt], ah[mt], bl0, bl1);
                if (XLO) mma_bf16(acc[mt][nt], al[mt], bh0, bh1);
            }
        }
    }

    // epilogue: scale by dinv[row], store fp16 H'
#pragma unroll
    for (int mt = 0; mt < 2; mt++) {
        int rbase = row0 + wr * 32 + mt * 16 + g;
        float d0 = (rbase < NV) ? g_dinv[rbase] : 0.f;
        float d1 = (rbase + 8 < NV) ? g_dinv[rbase + 8] : 0.f;
#pragma unroll
        for (int nt = 0; nt < 8; nt++) {
            int col = wc * 64 + nt * 8 + q4 * 2;
            if (rbase < NV)
                *(__half2*)(H + rbase * HIDDEN + col) =
                    __floats2half2_rn(acc[mt][nt][0] * d0, acc[mt][nt][1] * d0);
            if (rbase + 8 < NV)
                *(__half2*)(H + (rbase + 8) * HIDDEN + col) =
                    __floats2half2_rn(acc[mt][nt][2] * d1, acc[mt][nt][3] * d1);
        }
    }
}

// ---------------- aggregation: one warp per dst row ---------------------------
__device__ __forceinline__ float4 h4_to_f4(uint2 u) {
    float2 f0 = __half22float2(*(__half2*)&u.x);
    float2 f1 = __half22float2(*(__half2*)&u.y);
    return make_float4(f0.x, f0.y, f1.x, f1.y);
}

// OUT[row] = ReLU( dd * ( H'[row] + sum_e H'[src_e] ) + bias ),  dd = dinv[row]
__global__ void agg_kernel(const __half* __restrict__ H,
                           const float* __restrict__ bias,
                           __half* __restrict__ OUT) {
    int row = (blockIdx.x * blockDim.x + threadIdx.x) >> 5;
    int lane = threadIdx.x & 31;
    if (row >= NV) return;
    int beg = g_rowptr[row], end = g_rowptr[row + 1];
    float dd = g_dinv[row];
    const uint2* Hp = (const uint2*)H;
    float4 es = make_float4(0.f, 0.f, 0.f, 0.f);
    int e = beg;
    for (; e + 3 < end; e += 4) {
        int s0 = g_esrc[e];
        int s1 = g_esrc[e + 1];
        int s2 = g_esrc[e + 2];
        int s3 = g_esrc[e + 3];
        float4 v0 = h4_to_f4(Hp[s0 * 32 + lane]);
        float4 v1 = h4_to_f4(Hp[s1 * 32 + lane]);
        float4 v2 = h4_to_f4(Hp[s2 * 32 + lane]);
        float4 v3 = h4_to_f4(Hp[s3 * 32 + lane]);
        es.x += (v0.x + v1.x) + (v2.x + v3.x);
        es.y += (v0.y + v1.y) + (v2.y + v3.y);
        es.z += (v0.z + v1.z) + (v2.z + v3.z);
        es.w += (v0.w + v1.w) + (v2.w + v3.w);
    }
    for (; e < end; e++) {
        float4 v = h4_to_f4(Hp[g_esrc[e] * 32 + lane]);
        es.x += v.x; es.y += v.y; es.z += v.z; es.w += v.w;
    }
    float4 h = h4_to_f4(Hp[row * 32 + lane]);
    float4 b = *((const float4*)bias + lane);
    uint2 o;
    *(__half2*)&o.x = __floats2half2_rn(fmaxf((h.x + es.x) * dd + b.x, 0.f),
                                        fmaxf((h.y + es.y) * dd + b.y, 0.f));
    *(__half2*)&o.y = __floats2half2_rn(fmaxf((h.z + es.z) * dd + b.z, 0.f),
                                        fmaxf((h.w + es.w) * dd + b.w, 0.f));
    *((uint2*)OUT + row * 32 + lane) = o;
}

// ---------------- pooling over sorted batch (fp16 in, already ReLU'd) ----------
__global__ void pool_kernel(const __half* __restrict__ X, const int* __restrict__ batch) {
    int c = threadIdx.x;
    int row0 = blockIdx.x * POOL_ROWS;
    if (row0 >= NV) return;
    int rend = min(row0 + POOL_ROWS, NV);
    float acc = 0.f;
    int cur = batch[row0];
    int runstart = row0;
    for (int r = row0; r < rend; r++) {
        int b = batch[r];
        if (b != cur) {
            atomicAdd(&g_summ[cur * HIDDEN + c], acc);
            if (c == 0) atomicAdd(&g_cnt[cur], (float)(r - runstart));
            acc = 0.f; cur = b; runstart = r;
        }
        acc += __half2float(X[(long long)r * HIDDEN + c]);
    }
    atomicAdd(&g_summ[cur * HIDDEN + c], acc);
    if (c == 0) atomicAdd(&g_cnt[cur], (float)(rend - runstart));
}

// ---------------- head: pooled @ W_out + b_out, layernorm; self-cleaning tail --
__global__ void final_kernel(const float* __restrict__ Wo, const float* __restrict__ bo,
                             const float* __restrict__ gamma, const float* __restrict__ beta,
                             float* __restrict__ out) {
    __shared__ float p[HIDDEN];
    __shared__ float rs[DMODEL];
    __shared__ float rq[DMODEL];
    int b = blockIdx.x, c = threadIdx.x;
    if (c < HIDDEN) {
        float cnt = fmaxf(g_cnt[b], 1.f);
        p[c] = g_summ[b * HIDDEN + c] / cnt;
    }
    __syncthreads();
    // self-clean this block's own pooling slots (read above, safe per-block)
    if (c < HIDDEN) g_summ[b * HIDDEN + c] = 0.f;
    if (c == 0) g_cnt[b] = 0.f;

    float y = bo[c];
#pragma unroll 8
    for (int k = 0; k < HIDDEN; k++) y += p[k] * Wo[k * DMODEL + c];
    rs[c] = y;
    rq[c] = y * y;
    __syncthreads();
    for (int s = DMODEL / 2; s > 0; s >>= 1) {
        if (c < s) { rs[c] += rs[c + s]; rq[c] += rq[c + s]; }
        __syncthreads();
    }
    float mu = rs[0] / (float)DMODEL;
    float var = rq[0] / (float)DMODEL - mu * mu;
    out[b * DMODEL + c] = (y - mu) * rsqrtf(var + EPSV) * gamma[c] + beta[c];

    // self-clean the setup state for the next call/replay (not read by this kernel)
    int gtid = b * DMODEL + c;                      // 0 .. 16383
    for (int i = gtid; i < NV; i += BB * DMODEL) g_deg[i] = 0;
    if (gtid < NBLK) g_desc[gtid] = 0ULL;
}

// ---------------- launch ----------------
extern "C" void kernel_launch(void* const* d_in, const int* in_sizes, int n_in,
                              void* d_out, int out_size) {
    const float* vertices = (const float*)d_in[0];
    const int*   eidx     = (const int*)d_in[1];
    const int*   batch    = (const int*)d_in[2];
    const float* W_in     = (const float*)d_in[3];
    const float* b_in     = (const float*)d_in[4];
    const float* W1       = (const float*)d_in[5];
    const float* b1       = (const float*)d_in[6];
    const float* W2       = (const float*)d_in[7];
    const float* b2       = (const float*)d_in[8];
    const float* W3       = (const float*)d_in[9];
    const float* b3       = (const float*)d_in[10];
    const float* W_out    = (const float*)d_in[11];
    const float* b_out    = (const float*)d_in[12];
    const float* gamma    = (const float*)d_in[13];
    const float* beta     = (const float*)d_in[14];
    const int* src = eidx;
    const int* dst = eidx + EE;
    float* out = (float*)d_out;

    __half *ph, *pxa, *pxb;
    __nv_bfloat16 *pwh, *pwl;
    cudaGetSymbolAddress((void**)&ph, g_h16);
    cudaGetSymbolAddress((void**)&pxa, g_x16a);
    cudaGetSymbolAddress((void**)&pxb, g_x16b);
    cudaGetSymbolAddress((void**)&pwh, g_wh);
    cudaGetSymbolAddress((void**)&pwl, g_wl);

    cudaFuncSetAttribute((gemm_tc_kernel<true, true>),
                         cudaFuncAttributeMaxDynamicSharedMemorySize, SMEM_L1);
    cudaFuncSetAttribute((gemm_tc_kernel<false, false>),
                         cudaFuncAttributeMaxDynamicSharedMemorySize, SMEM_L23);

    deg_kernel<<<(EE / 4 + 255) / 256, 256>>>((const int4*)dst);
    wsplit_kernel<<<(3 * HIDDEN * HIDDEN + 255) / 256, 256>>>(W1, W2, W3);
    scan_kernel<<<NBLK, 256>>>();
    sort_kernel<<<(EE / 4 + 255) / 256, 256>>>((const int4*)src, (const int4*)dst);

    int gblocks = (NV + 127) / 128;
    int ablocks = (int)(((long long)NV * 32 + 255) / 256);

    // layer 1: input projection fused into GEMM (fp32 X -> full hi/lo split)
    gemm_tc_kernel<true, true><<<gblocks, 256, SMEM_L1>>>(
        vertices, (const __half*)0, W_in, b_in,
        pwh + 0 * HIDDEN * HIDDEN, pwl + 0 * HIDDEN * HIDDEN, ph);
    agg_kernel<<<ablocks, 256>>>(ph, b1, pxa);

    // layers 2,3: fp16 X -> hi-only (2 MMAs)
    gemm_tc_kernel<false, false><<<gblocks, 256, SMEM_L23>>>(
        (const float*)0, pxa, (const float*)0, (const float*)0,
        pwh + 1 * HIDDEN * HIDDEN, pwl + 1 * HIDDEN * HIDDEN, ph);
    agg_kernel<<<ablocks, 256>>>(ph, b2, pxb);

    gemm_tc_kernel<false, false><<<gblocks, 256, SMEM_L23>>>(
        (const float*)0, pxb, (const float*)0, (const float*)0,
        pwh + 2 * HIDDEN * HIDDEN, pwl + 2 * HIDDEN * HIDDEN, ph);
    agg_kernel<<<ablocks, 256>>>(ph, b3, pxa);

    pool_kernel<<<(NV + POOL_ROWS - 1) / POOL_ROWS, POOL_ROWS>>>(pxa, batch);
    final_kernel<<<BB, DMODEL>>>(W_out, b_out, gamma, beta, out);
}

// round 13
// speedup vs baseline: 1.1787x; 1.0121x over previous
#include <cuda_runtime.h>
#include <cuda_bf16.h>
#include <cuda_fp16.h>
#include <cstdint>

#define NV 100000
#define EE 1600000
#define BB 64
#define HIDDEN 128
#define DMODEL 256
#define EPSV 1e-5f
#define POOL_ROWS 128
#define NBLK ((NV + 255) / 256)   // 391 scan blocks

// ---------------- scratch (static device globals; no allocation) ----------------
// NOTE: g_deg, g_desc, g_summ, g_cnt rely on the self-cleaning invariant:
// zero at module load, re-zeroed by final_kernel's tail every call.
__device__ __half g_h16[NV * HIDDEN];   // dinv-scaled pre-agg features H' (fp16)
__device__ __half g_x16a[NV * HIDDEN];  // activation ping (fp16)
__device__ __half g_x16b[NV * HIDDEN];  // activation pong (fp16)
__device__ float g_dinv[NV];            // deg^{-1/2}
__device__ int   g_deg[NV];             // in-degree
__device__ int   g_rowptr[NV + 1];      // CSR offsets (by dst)
__device__ int   g_pos[NV];             // running insert positions for sort
__device__ unsigned long long g_desc[NBLK];  // decoupled-lookback descriptors
__device__ int   g_esrc[EE];            // sorted edges: src only (dinv folded into H')
__device__ float g_summ[BB * HIDDEN];   // pooled sums
__device__ float g_cnt[BB];             // pooled counts
__device__ __nv_bfloat16 g_wh[3][HIDDEN * HIDDEN];  // pre-split W, transposed [n][k]
__device__ __nv_bfloat16 g_wl[3][HIDDEN * HIDDEN];

// ---------------- setup kernels ----------------
__global__ void deg_kernel(const int4* __restrict__ dst4) {
    int e = blockIdx.x * blockDim.x + threadIdx.x;
    if (e < EE / 4) {
        int4 d = dst4[e];
        atomicAdd(&g_deg[d.x], 1);
        atomicAdd(&g_deg[d.y], 1);
        atomicAdd(&g_deg[d.z], 1);
        atomicAdd(&g_deg[d.w], 1);
    }
}

// pre-split the three layer weights into bf16 hi/lo, transposed [n][k] packed
__global__ void wsplit_kernel(const float* __restrict__ W1,
                              const float* __restrict__ W2,
                              const float* __restrict__ W3) {
    int i = blockIdx.x * blockDim.x + threadIdx.x;   // 0 .. 3*16384-1
    if (i >= 3 * HIDDEN * HIDDEN) return;
    int l = i >> 14, idx = i & 16383;
    const float* W = (l == 0) ? W1 : (l == 1) ? W2 : W3;
    int k = idx >> 7, n = idx & 127;
    float w = W[idx];
    __nv_bfloat16 wh = __float2bfloat16_rn(w);
    g_wh[l][n * HIDDEN + k] = wh;
    g_wl[l][n * HIDDEN + k] = __float2bfloat16_rn(w - __bfloat162float(wh));
}

// --- single-pass decoupled-lookback exclusive scan of g_deg ---
__global__ void scan_kernel() {
    __shared__ int s[256];
    __shared__ int sh_ex;
    int tid = threadIdx.x;
    int b = blockIdx.x;
    int i = b * 256 + tid;
    int v = (i < NV) ? g_deg[i] : 0;
    s[tid] = v;
    __syncthreads();
#pragma unroll
    for (int off = 1; off < 256; off <<= 1) {
        int t = (tid >= off) ? s[tid - off] : 0;
        __syncthreads();
        s[tid] += t;
        __syncthreads();
    }
    int incl = s[tid];
    int total = s[255];

    if (tid == 0) {
        unsigned long long ex = 0;
        if (b > 0) {
            atomicExch(&g_desc[b], (1ULL << 32) | (unsigned int)total);
            int j = b - 1;
            while (true) {
                unsigned long long d = atomicAdd(&g_desc[j], 0ULL);
                unsigned int st = (unsigned int)(d >> 32);
                if (st == 2u) { ex += (unsigned int)d; break; }
                if (st == 1u) { ex += (unsigned int)d; j--; }
            }
        }
        atomicExch(&g_desc[b], (2ULL << 32) | (unsigned int)(ex + (unsigned int)total));
        sh_ex = (int)ex;
    }
    __syncthreads();
    int excl = sh_ex + incl - v;
    if (i < NV) {
        g_rowptr[i] = excl;
        g_pos[i] = excl;
        g_dinv[i] = rsqrtf((float)v + 1.f);
    }
    if (i == NV - 1) g_rowptr[NV] = excl + v;
}

// counting-sort edges by dst; scalar 1 edge/thread (max warp-level parallelism)
__global__ void sort_kernel(const int* __restrict__ src, const int* __restrict__ dst) {
    int e = blockIdx.x * blockDim.x + threadIdx.x;
    if (e >= EE) return;
    int d = dst[e];
    int p = atomicAdd(&g_pos[d], 1);
    g_esrc[p] = src[e];
}

// ---------------- tensor-core GEMM: H' = dinv * (X @ W)  (bf16 split) ----------
__device__ __forceinline__ void mma_bf16(float* c, const uint32_t* a,
                                         uint32_t b0, uint32_t b1) {
    asm volatile(
        "mma.sync.aligned.m16n8k16.row.col.f32.bf16.bf16.f32 "
        "{%0,%1,%2,%3}, {%4,%5,%6,%7}, {%8,%9}, {%0,%1,%2,%3};\n"
        : "+f"(c[0]), "+f"(c[1]), "+f"(c[2]), "+f"(c[3])
        : "r"(a[0]), "r"(a[1]), "r"(a[2]), "r"(a[3]), "r"(b0), "r"(b1));
}

#define BST 136          // smem row stride in bf16 elements
#define BSTW 68          // same, in 32-bit words
#define XTILE (128 * BST)
#define SMEM_L1 (4 * XTILE * 2 + 512 * 4)   // Xh,Xl,Wh,Wl + W_in/b_in floats
#define SMEM_L23 (3 * XTILE * 2)            // Xh,Wh,Wl

template <bool FUSE_IN, bool XLO>
__global__ void gemm_tc_kernel(const float* __restrict__ V,
                               const __half* __restrict__ X16,
                               const float* __restrict__ Wi,
                               const float* __restrict__ bi,
                               const __nv_bfloat16* __restrict__ Whg,
                               const __nv_bfloat16* __restrict__ Wlg,
                               __half* __restrict__ H) {
    extern __shared__ __nv_bfloat16 sb[];
    __nv_bfloat16* Xh = sb;
    __nv_bfloat16* Xl = sb + XTILE;                    // only used when XLO
    __nv_bfloat16* Wh = sb + (XLO ? 2 : 1) * XTILE;
    __nv_bfloat16* Wl = sb + (XLO ? 3 : 2) * XTILE;
    float* sWin = (float*)(sb + 4 * XTILE);            // only used when FUSE_IN
    int t = threadIdx.x;
    int row0 = blockIdx.x * 128;

    // pre-split W (bf16, packed [n][k]) -> padded smem via float4 copies
#pragma unroll
    for (int i = 0; i < 8; i++) {
        int w4 = i * 256 + t;                // float4 slot 0..2047
        int n = w4 >> 4, kq = w4 & 15;       // 16 float4 per 128-half row
        *(float4*)(Wh + n * BST + kq * 8) = *((const float4*)Whg + w4);
        *(float4*)(Wl + n * BST + kq * 8) = *((const float4*)Wlg + w4);
    }
    if (FUSE_IN) {
        for (int i = t; i < 512; i += 256)
            sWin[i] = (i < 384) ? Wi[i] : bi[i - 384];
        __syncthreads();
    }

#pragma unroll
    for (int i = 0; i < 16; i++) {
        int idx = i * 256 + t;
        int r = idx >> 5, q = idx & 31;
        int gr = row0 + r;
        float4 v = make_float4(0.f, 0.f, 0.f, 0.f);
        if (FUSE_IN) {
            float v0 = 0.f, v1 = 0.f, v2 = 0.f;
            if (gr < NV) {
                v0 = V[gr * 3 + 0]; v1 = V[gr * 3 + 1]; v2 = V[gr * 3 + 2];
            }
            int c = q * 4;
            float* pv = &v.x;
#pragma unroll
            for (int j = 0; j < 4; j++) {
                int cc = c + j;
                pv[j] = sWin[384 + cc] + v0 * sWin[cc] + v1 * sWin[128 + cc]
                        + v2 * sWin[256 + cc];
            }
        } else if (gr < NV) {
            uint2 u = *((const uint2*)X16 + gr * 32 + q);
            float2 f0 = __half22float2(*(__half2*)&u.x);
            float2 f1 = __half22float2(*(__half2*)&u.y);
            v = make_float4(f0.x, f0.y, f1.x, f1.y);
        }
        __nv_bfloat162 h0 = __floats2bfloat162_rn(v.x, v.y);
        __nv_bfloat162 h1 = __floats2bfloat162_rn(v.z, v.w);
        int base = r * BST + q * 4;
        *(__nv_bfloat162*)(Xh + base) = h0;
        *(__nv_bfloat162*)(Xh + base + 2) = h1;
        if (XLO) {
            float2 hf0 = __bfloat1622float2(h0);
            float2 hf1 = __bfloat1622float2(h1);
            *(__nv_bfloat162*)(Xl + base) = __floats2bfloat162_rn(v.x - hf0.x, v.y - hf0.y);
            *(__nv_bfloat162*)(Xl + base + 2) = __floats2bfloat162_rn(v.z - hf1.x, v.w - hf1.y);
        }
    }
    __syncthreads();

    int w = t >> 5, lane = t & 31;
    int wr = w >> 1, wc = w & 1;
    int g = lane >> 2, q4 = lane & 3;

    float acc[2][8][4];
#pragma unroll
    for (int mt = 0; mt < 2; mt++)
#pragma unroll
        for (int nt = 0; nt < 8; nt++)
#pragma unroll
            for (int j = 0; j < 4; j++) acc[mt][nt][j] = 0.f;

    const uint32_t* pXh = (const uint32_t*)Xh;
    const uint32_t* pXl = (const uint32_t*)Xl;
    const uint32_t* pWh = (const uint32_t*)Wh;
    const uint32_t* pWl = (const uint32_t*)Wl;

#pragma unroll
    for (int ks = 0; ks < 8; ks++) {
        int kw = ks * 8 + q4;
        uint32_t ah[2][4], al[2][4];
#pragma unroll
        for (int mt = 0; mt < 2; mt++) {
            int r = wr * 32 + mt * 16 + g;
            ah[mt][0] = pXh[r * BSTW + kw];
            ah[mt][1] = pXh[(r + 8) * BSTW + kw];
            ah[mt][2] = pXh[r * BSTW + kw + 4];
            ah[mt][3] = pXh[(r + 8) * BSTW + kw + 4];
            if (XLO) {
                al[mt][0] = pXl[r * BSTW + kw];
                al[mt][1] = pXl[(r + 8) * BSTW + kw];
                al[mt][2] = pXl[r * BSTW + kw + 4];
                al[mt][3] = pXl[(r + 8) * BSTW + kw + 4];
            }
        }
#pragma unroll
        for (int nt = 0; nt < 8; nt++) {
            int n = wc * 64 + nt * 8 + g;
            uint32_t bh0 = pWh[n * BSTW + kw];
            uint32_t bh1 = pWh[n * BSTW + kw + 4];
            uint32_t bl0 = pWl[n * BSTW + kw];
            uint32_t bl1 = pWl[n * BSTW + kw + 4];
#pragma unroll
            for (int mt = 0; mt < 2; mt++) {
                mma_bf16(acc[mt][nt], ah[mt], bh0, bh1);
                mma_bf16(acc[mt][nt], ah[mt], bl0, bl1);
                if (XLO) mma_bf16(acc[mt][nt], al[mt], bh0, bh1);
            }
        }
    }

    // epilogue: scale by dinv[row], store fp16 H'
#pragma unroll
    for (int mt = 0; mt < 2; mt++) {
        int rbase = row0 + wr * 32 + mt * 16 + g;
        float d0 = (rbase < NV) ? g_dinv[rbase] : 0.f;
        float d1 = (rbase + 8 < NV) ? g_dinv[rbase + 8] : 0.f;
#pragma unroll
        for (int nt = 0; nt < 8; nt++) {
            int col = wc * 64 + nt * 8 + q4 * 2;
            if (rbase < NV)
                *(__half2*)(H + rbase * HIDDEN + col) =
                    __floats2half2_rn(acc[mt][nt][0] * d0, acc[mt][nt][1] * d0);
            if (rbase + 8 < NV)
                *(__half2*)(H + (rbase + 8) * HIDDEN + col) =
                    __floats2half2_rn(acc[mt][nt][2] * d1, acc[mt][nt][3] * d1);
        }
    }
}

// ---------------- aggregation: one warp per dst row ---------------------------
__device__ __forceinline__ float4 h4_to_f4(uint2 u) {
    float2 f0 = __half22float2(*(__half2*)&u.x);
    float2 f1 = __half22float2(*(__half2*)&u.y);
    return make_float4(f0.x, f0.y, f1.x, f1.y);
}

// OUT[row] = ReLU( dd * ( H'[row] + sum_e H'[src_e] ) + bias ),  dd = dinv[row]
__global__ void agg_kernel(const __half* __restrict__ H,
                           const float* __restrict__ bias,
                           __half* __restrict__ OUT) {
    int row = (blockIdx.x * blockDim.x + threadIdx.x) >> 5;
    int lane = threadIdx.x & 31;
    if (row >= NV) return;
    int beg = g_rowptr[row], end = g_rowptr[row + 1];
    float dd = g_dinv[row];
    const uint2* Hp = (const uint2*)H;
    float4 es = make_float4(0.f, 0.f, 0.f, 0.f);
    int e = beg;
    for (; e + 3 < end; e += 4) {
        int s0 = g_esrc[e];
        int s1 = g_esrc[e + 1];
        int s2 = g_esrc[e + 2];
        int s3 = g_esrc[e + 3];
        float4 v0 = h4_to_f4(Hp[s0 * 32 + lane]);
        float4 v1 = h4_to_f4(Hp[s1 * 32 + lane]);
        float4 v2 = h4_to_f4(Hp[s2 * 32 + lane]);
        float4 v3 = h4_to_f4(Hp[s3 * 32 + lane]);
        es.x += (v0.x + v1.x) + (v2.x + v3.x);
        es.y += (v0.y + v1.y) + (v2.y + v3.y);
        es.z += (v0.z + v1.z) + (v2.z + v3.z);
        es.w += (v0.w + v1.w) + (v2.w + v3.w);
    }
    for (; e < end; e++) {
        float4 v = h4_to_f4(Hp[g_esrc[e] * 32 + lane]);
        es.x += v.x; es.y += v.y; es.z += v.z; es.w += v.w;
    }
    float4 h = h4_to_f4(Hp[row * 32 + lane]);
    float4 b = *((const float4*)bias + lane);
    uint2 o;
    *(__half2*)&o.x = __floats2half2_rn(fmaxf((h.x + es.x) * dd + b.x, 0.f),
                                        fmaxf((h.y + es.y) * dd + b.y, 0.f));
    *(__half2*)&o.y = __floats2half2_rn(fmaxf((h.z + es.z) * dd + b.z, 0.f),
                                        fmaxf((h.w + es.w) * dd + b.w, 0.f));
    *((uint2*)OUT + row * 32 + lane) = o;
}

// ---------------- pooling over sorted batch (fp16 in, already ReLU'd) ----------
__global__ void pool_kernel(const __half* __restrict__ X, const int* __restrict__ batch) {
    int c = threadIdx.x;
    int row0 = blockIdx.x * POOL_ROWS;
    if (row0 >= NV) return;
    int rend = min(row0 + POOL_ROWS, NV);
    float acc = 0.f;
    int cur = batch[row0];
    int runstart = row0;
    for (int r = row0; r < rend; r++) {
        int b = batch[r];
        if (b != cur) {
            atomicAdd(&g_summ[cur * HIDDEN + c], acc);
            if (c == 0) atomicAdd(&g_cnt[cur], (float)(r - runstart));
            acc = 0.f; cur = b; runstart = r;
        }
        acc += __half2float(X[(long long)r * HIDDEN + c]);
    }
    atomicAdd(&g_summ[cur * HIDDEN + c], acc);
    if (c == 0) atomicAdd(&g_cnt[cur], (float)(rend - runstart));
}

// ---------------- head: pooled @ W_out + b_out, layernorm; self-cleaning tail --
__global__ void final_kernel(const float* __restrict__ Wo, const float* __restrict__ bo,
                             const float* __restrict__ gamma, const float* __restrict__ beta,
                             float* __restrict__ out) {
    __shared__ float p[HIDDEN];
    __shared__ float rs[DMODEL];
    __shared__ float rq[DMODEL];
    int b = blockIdx.x, c = threadIdx.x;
    if (c < HIDDEN) {
        float cnt = fmaxf(g_cnt[b], 1.f);
        p[c] = g_summ[b * HIDDEN + c] / cnt;
    }
    __syncthreads();
    // self-clean this block's own pooling slots (read above, safe per-block)
    if (c < HIDDEN) g_summ[b * HIDDEN + c] = 0.f;
    if (c == 0) g_cnt[b] = 0.f;

    float y = bo[c];
#pragma unroll 8
    for (int k = 0; k < HIDDEN; k++) y += p[k] * Wo[k * DMODEL + c];
    rs[c] = y;
    rq[c] = y * y;
    __syncthreads();
    for (int s = DMODEL / 2; s > 0; s >>= 1) {
        if (c < s) { rs[c] += rs[c + s]; rq[c] += rq[c + s]; }
        __syncthreads();
    }
    float mu = rs[0] / (float)DMODEL;
    float var = rq[0] / (float)DMODEL - mu * mu;
    out[b * DMODEL + c] = (y - mu) * rsqrtf(var + EPSV) * gamma[c] + beta[c];

    // self-clean the setup state for the next call/replay (not read by this kernel)
    int gtid = b * DMODEL + c;                      // 0 .. 16383
    for (int i = gtid; i < NV; i += BB * DMODEL) g_deg[i] = 0;
    if (gtid < NBLK) g_desc[gtid] = 0ULL;
}

// ---------------- launch ----------------
extern "C" void kernel_launch(void* const* d_in, const int* in_sizes, int n_in,
                              void* d_out, int out_size) {
    const float* vertices = (const float*)d_in[0];
    const int*   eidx     = (const int*)d_in[1];
    const int*   batch    = (const int*)d_in[2];
    const float* W_in     = (const float*)d_in[3];
    const float* b_in     = (const float*)d_in[4];
    const float* W1       = (const float*)d_in[5];
    const float* b1       = (const float*)d_in[6];
    const float* W2       = (const float*)d_in[7];
    const float* b2       = (const float*)d_in[8];
    const float* W3       = (const float*)d_in[9];
    const float* b3       = (const float*)d_in[10];
    const float* W_out    = (const float*)d_in[11];
    const float* b_out    = (const float*)d_in[12];
    const float* gamma    = (const float*)d_in[13];
    const float* beta     = (const float*)d_in[14];
    const int* src = eidx;
    const int* dst = eidx + EE;
    float* out = (float*)d_out;

    __half *ph, *pxa, *pxb;
    __nv_bfloat16 *pwh, *pwl;
    cudaGetSymbolAddress((void**)&ph, g_h16);
    cudaGetSymbolAddress((void**)&pxa, g_x16a);
    cudaGetSymbolAddress((void**)&pxb, g_x16b);
    cudaGetSymbolAddress((void**)&pwh, g_wh);
    cudaGetSymbolAddress((void**)&pwl, g_wl);

    cudaFuncSetAttribute((gemm_tc_kernel<true, true>),
                         cudaFuncAttributeMaxDynamicSharedMemorySize, SMEM_L1);
    cudaFuncSetAttribute((gemm_tc_kernel<false, false>),
                         cudaFuncAttributeMaxDynamicSharedMemorySize, SMEM_L23);

    // second stream for capture-safe fork/join overlap (no device memory involved;
    // kernel_launch runs only for correctness + capture, so per-call create is fine)
    cudaStream_t s2;
    cudaStreamCreateWithFlags(&s2, cudaStreamNonBlocking);
    cudaEvent_t ev_fork, ev_scan, ev_g1;
    cudaEventCreateWithFlags(&ev_fork, cudaEventDisableTiming);
    cudaEventCreateWithFlags(&ev_scan, cudaEventDisableTiming);
    cudaEventCreateWithFlags(&ev_g1, cudaEventDisableTiming);

    int gblocks = (NV + 127) / 128;
    int ablocks = (int)(((long long)NV * 32 + 255) / 256);

    // fork s2 from the capture stream
    cudaEventRecord(ev_fork, 0);
    cudaStreamWaitEvent(s2, ev_fork, 0);

    // s2: wsplit (independent)         main: deg -> scan
    wsplit_kernel<<<(3 * HIDDEN * HIDDEN + 255) / 256, 256, 0, s2>>>(W1, W2, W3);
    deg_kernel<<<(EE / 4 + 255) / 256, 256>>>((const int4*)dst);
    scan_kernel<<<NBLK, 256>>>();
    cudaEventRecord(ev_scan, 0);

    // s2: GEMM1 (needs dinv from scan + wsplit)   main: sort (needs scan)
    cudaStreamWaitEvent(s2, ev_scan, 0);
    gemm_tc_kernel<true, true><<<gblocks, 256, SMEM_L1, s2>>>(
        vertices, (const __half*)0, W_in, b_in,
        pwh + 0 * HIDDEN * HIDDEN, pwl + 0 * HIDDEN * HIDDEN, ph);
    cudaEventRecord(ev_g1, s2);
    sort_kernel<<<(EE + 255) / 256, 256>>>(src, dst);

    // join: agg1 needs sort (main) + GEMM1 (s2)
    cudaStreamWaitEvent(0, ev_g1, 0);
    agg_kernel<<<ablocks, 256>>>(ph, b1, pxa);

    // layers 2,3: fp16 X -> hi-only (2 MMAs), serial chain on main stream
    gemm_tc_kernel<false, false><<<gblocks, 256, SMEM_L23>>>(
        (const float*)0, pxa, (const float*)0, (const float*)0,
        pwh + 1 * HIDDEN * HIDDEN, pwl + 1 * HIDDEN * HIDDEN, ph);
    agg_kernel<<<ablocks, 256>>>(ph, b2, pxb);

    gemm_tc_kernel<false, false><<<gblocks, 256, SMEM_L23>>>(
        (const float*)0, pxb, (const float*)0, (const float*)0,
        pwh + 2 * HIDDEN * HIDDEN, pwl + 2 * HIDDEN * HIDDEN, ph);
    agg_kernel<<<ablocks, 256>>>(ph, b3, pxa);

    pool_kernel<<<(NV + POOL_ROWS - 1) / POOL_ROWS, POOL_ROWS>>>(pxa, batch);
    final_kernel<<<BB, DMODEL>>>(W_out, b_out, gamma, beta, out);

    cudaEventDestroy(ev_fork);
    cudaEventDestroy(ev_scan);
    cudaEventDestroy(ev_g1);
    cudaStreamDestroy(s2);
}

// round 14
// speedup vs baseline: 1.3529x; 1.1479x over previous
#include <cuda_runtime.h>
#include <cuda_bf16.h>
#include <cuda_fp16.h>
#include <cstdint>

#define NV 100000
#define EE 1600000
#define BB 64
#define HIDDEN 128
#define DMODEL 256
#define EPSV 1e-5f
#define POOL_ROWS 128
#define NBLK ((NV + 255) / 256)   // 391 scan blocks

// ---------------- scratch (static device globals; no allocation) ----------------
// NOTE: g_deg, g_desc, g_summ, g_cnt rely on the self-cleaning invariant:
// zero at module load, re-zeroed by final_kernel's tail every call.
__device__ __half g_h16[NV * HIDDEN];   // dinv-scaled pre-agg features H' (fp16)
__device__ __half g_x16a[NV * HIDDEN];  // activation ping (fp16)
__device__ __half g_x16b[NV * HIDDEN];  // activation pong (fp16)
__device__ float g_dinv[NV];            // deg^{-1/2}
__device__ int   g_deg[NV];             // in-degree
__device__ int   g_rowptr[NV + 1];      // CSR offsets (by dst)
__device__ int   g_pos[NV];             // running insert positions for sort
__device__ unsigned long long g_desc[NBLK];  // decoupled-lookback descriptors
__device__ int   g_esrc[EE];            // sorted edges: src only (dinv folded into H')
__device__ float g_summ[BB * HIDDEN];   // pooled sums
__device__ float g_cnt[BB];             // pooled counts
__device__ __nv_bfloat16 g_wh[3][HIDDEN * HIDDEN];  // bf16 W, transposed [n][k]

// ---------------- setup kernels ----------------
__global__ void deg_kernel(const int4* __restrict__ dst4) {
    int e = blockIdx.x * blockDim.x + threadIdx.x;
    if (e < EE / 4) {
        int4 d = dst4[e];
        atomicAdd(&g_deg[d.x], 1);
        atomicAdd(&g_deg[d.y], 1);
        atomicAdd(&g_deg[d.z], 1);
        atomicAdd(&g_deg[d.w], 1);
    }
}

// convert the three layer weights to bf16, transposed [n][k] packed
__global__ void wsplit_kernel(const float* __restrict__ W1,
                              const float* __restrict__ W2,
                              const float* __restrict__ W3) {
    int i = blockIdx.x * blockDim.x + threadIdx.x;   // 0 .. 3*16384-1
    if (i >= 3 * HIDDEN * HIDDEN) return;
    int l = i >> 14, idx = i & 16383;
    const float* W = (l == 0) ? W1 : (l == 1) ? W2 : W3;
    int k = idx >> 7, n = idx & 127;
    g_wh[l][n * HIDDEN + k] = __float2bfloat16_rn(W[idx]);
}

// --- single-pass decoupled-lookback exclusive scan of g_deg ---
__global__ void scan_kernel() {
    __shared__ int s[256];
    __shared__ int sh_ex;
    int tid = threadIdx.x;
    int b = blockIdx.x;
    int i = b * 256 + tid;
    int v = (i < NV) ? g_deg[i] : 0;
    s[tid] = v;
    __syncthreads();
#pragma unroll
    for (int off = 1; off < 256; off <<= 1) {
        int t = (tid >= off) ? s[tid - off] : 0;
        __syncthreads();
        s[tid] += t;
        __syncthreads();
    }
    int incl = s[tid];
    int total = s[255];

    if (tid == 0) {
        unsigned long long ex = 0;
        if (b > 0) {
            atomicExch(&g_desc[b], (1ULL << 32) | (unsigned int)total);
            int j = b - 1;
            while (true) {
                unsigned long long d = atomicAdd(&g_desc[j], 0ULL);
                unsigned int st = (unsigned int)(d >> 32);
                if (st == 2u) { ex += (unsigned int)d; break; }
                if (st == 1u) { ex += (unsigned int)d; j--; }
            }
        }
        atomicExch(&g_desc[b], (2ULL << 32) | (unsigned int)(ex + (unsigned int)total));
        sh_ex = (int)ex;
    }
    __syncthreads();
    int excl = sh_ex + incl - v;
    if (i < NV) {
        g_rowptr[i] = excl;
        g_pos[i] = excl;
        g_dinv[i] = rsqrtf((float)v + 1.f);
    }
    if (i == NV - 1) g_rowptr[NV] = excl + v;
}

// counting-sort edges by dst; scalar 1 edge/thread (max warp-level parallelism)
__global__ void sort_kernel(const int* __restrict__ src, const int* __restrict__ dst) {
    int e = blockIdx.x * blockDim.x + threadIdx.x;
    if (e >= EE) return;
    int d = dst[e];
    int p = atomicAdd(&g_pos[d], 1);
    g_esrc[p] = src[e];
}

// ---------------- tensor-core GEMM: H' = dinv * (X @ W)  (bf16 single) ---------
__device__ __forceinline__ void mma_bf16(float* c, const uint32_t* a,
                                         uint32_t b0, uint32_t b1) {
    asm volatile(
        "mma.sync.aligned.m16n8k16.row.col.f32.bf16.bf16.f32 "
        "{%0,%1,%2,%3}, {%4,%5,%6,%7}, {%8,%9}, {%0,%1,%2,%3};\n"
        : "+f"(c[0]), "+f"(c[1]), "+f"(c[2]), "+f"(c[3])
        : "r"(a[0]), "r"(a[1]), "r"(a[2]), "r"(a[3]), "r"(b0), "r"(b1));
}

#define BST 136          // smem row stride in bf16 elements
#define BSTW 68          // same, in 32-bit words
#define XTILE (128 * BST)
#define SMEM_G (2 * XTILE * 2 + 512 * 4)   // Xh + Wh tiles + W_in/b_in floats

template <bool FUSE_IN>
__global__ void gemm_tc_kernel(const float* __restrict__ V,
                               const __half* __restrict__ X16,
                               const float* __restrict__ Wi,
                               const float* __restrict__ bi,
                               const __nv_bfloat16* __restrict__ Whg,
                               __half* __restrict__ H) {
    extern __shared__ __nv_bfloat16 sb[];
    __nv_bfloat16* Xh = sb;
    __nv_bfloat16* Wh = sb + XTILE;
    float* sWin = (float*)(sb + 2 * XTILE);            // only used when FUSE_IN
    int t = threadIdx.x;
    int row0 = blockIdx.x * 128;

    // bf16 W (packed [n][k]) -> padded smem via float4 copies
#pragma unroll
    for (int i = 0; i < 8; i++) {
        int w4 = i * 256 + t;                // float4 slot 0..2047
        int n = w4 >> 4, kq = w4 & 15;       // 16 float4 per 128-half row
        *(float4*)(Wh + n * BST + kq * 8) = *((const float4*)Whg + w4);
    }
    if (FUSE_IN) {
        for (int i = t; i < 512; i += 256)
            sWin[i] = (i < 384) ? Wi[i] : bi[i - 384];
        __syncthreads();
    }

#pragma unroll
    for (int i = 0; i < 16; i++) {
        int idx = i * 256 + t;
        int r = idx >> 5, q = idx & 31;
        int gr = row0 + r;
        float4 v = make_float4(0.f, 0.f, 0.f, 0.f);
        if (FUSE_IN) {
            float v0 = 0.f, v1 = 0.f, v2 = 0.f;
            if (gr < NV) {
                v0 = V[gr * 3 + 0]; v1 = V[gr * 3 + 1]; v2 = V[gr * 3 + 2];
            }
            int c = q * 4;
            float* pv = &v.x;
#pragma unroll
            for (int j = 0; j < 4; j++) {
                int cc = c + j;
                pv[j] = sWin[384 + cc] + v0 * sWin[cc] + v1 * sWin[128 + cc]
                        + v2 * sWin[256 + cc];
            }
        } else if (gr < NV) {
            uint2 u = *((const uint2*)X16 + gr * 32 + q);
            float2 f0 = __half22float2(*(__half2*)&u.x);
            float2 f1 = __half22float2(*(__half2*)&u.y);
            v = make_float4(f0.x, f0.y, f1.x, f1.y);
        }
        int base = r * BST + q * 4;
        *(__nv_bfloat162*)(Xh + base) = __floats2bfloat162_rn(v.x, v.y);
        *(__nv_bfloat162*)(Xh + base + 2) = __floats2bfloat162_rn(v.z, v.w);
    }
    __syncthreads();

    int w = t >> 5, lane = t & 31;
    int wr = w >> 1, wc = w & 1;
    int g = lane >> 2, q4 = lane & 3;

    float acc[2][8][4];
#pragma unroll
    for (int mt = 0; mt < 2; mt++)
#pragma unroll
        for (int nt = 0; nt < 8; nt++)
#pragma unroll
            for (int j = 0; j < 4; j++) acc[mt][nt][j] = 0.f;

    const uint32_t* pXh = (const uint32_t*)Xh;
    const uint32_t* pWh = (const uint32_t*)Wh;

#pragma unroll
    for (int ks = 0; ks < 8; ks++) {
        int kw = ks * 8 + q4;
        uint32_t ah[2][4];
#pragma unroll
        for (int mt = 0; mt < 2; mt++) {
            int r = wr * 32 + mt * 16 + g;
            ah[mt][0] = pXh[r * BSTW + kw];
            ah[mt][1] = pXh[(r + 8) * BSTW + kw];
            ah[mt][2] = pXh[r * BSTW + kw + 4];
            ah[mt][3] = pXh[(r + 8) * BSTW + kw + 4];
        }
#pragma unroll
        for (int nt = 0; nt < 8; nt++) {
            int n = wc * 64 + nt * 8 + g;
            uint32_t bh0 = pWh[n * BSTW + kw];
            uint32_t bh1 = pWh[n * BSTW + kw + 4];
#pragma unroll
            for (int mt = 0; mt < 2; mt++)
                mma_bf16(acc[mt][nt], ah[mt], bh0, bh1);
        }
    }

    // epilogue: scale by dinv[row], store fp16 H'
#pragma unroll
    for (int mt = 0; mt < 2; mt++) {
        int rbase = row0 + wr * 32 + mt * 16 + g;
        float d0 = (rbase < NV) ? g_dinv[rbase] : 0.f;
        float d1 = (rbase + 8 < NV) ? g_dinv[rbase + 8] : 0.f;
#pragma unroll
        for (int nt = 0; nt < 8; nt++) {
            int col = wc * 64 + nt * 8 + q4 * 2;
            if (rbase < NV)
                *(__half2*)(H + rbase * HIDDEN + col) =
                    __floats2half2_rn(acc[mt][nt][0] * d0, acc[mt][nt][1] * d0);
            if (rbase + 8 < NV)
                *(__half2*)(H + (rbase + 8) * HIDDEN + col) =
                    __floats2half2_rn(acc[mt][nt][2] * d1, acc[mt][nt][3] * d1);
        }
    }
}

// ---------------- aggregation: one warp per dst row ---------------------------
__device__ __forceinline__ float4 h4_to_f4(uint2 u) {
    float2 f0 = __half22float2(*(__half2*)&u.x);
    float2 f1 = __half22float2(*(__half2*)&u.y);
    return make_float4(f0.x, f0.y, f1.x, f1.y);
}

// OUT[row] = ReLU( dd * ( H'[row] + sum_e H'[src_e] ) + bias ),  dd = dinv[row]
__global__ void agg_kernel(const __half* __restrict__ H,
                           const float* __restrict__ bias,
                           __half* __restrict__ OUT) {
    int row = (blockIdx.x * blockDim.x + threadIdx.x) >> 5;
    int lane = threadIdx.x & 31;
    if (row >= NV) return;
    int beg = g_rowptr[row], end = g_rowptr[row + 1];
    float dd = g_dinv[row];
    const uint2* Hp = (const uint2*)H;
    float4 es = make_float4(0.f, 0.f, 0.f, 0.f);
    int e = beg;
    for (; e + 3 < end; e += 4) {
        int s0 = g_esrc[e];
        int s1 = g_esrc[e + 1];
        int s2 = g_esrc[e + 2];
        int s3 = g_esrc[e + 3];
        float4 v0 = h4_to_f4(Hp[s0 * 32 + lane]);
        float4 v1 = h4_to_f4(Hp[s1 * 32 + lane]);
        float4 v2 = h4_to_f4(Hp[s2 * 32 + lane]);
        float4 v3 = h4_to_f4(Hp[s3 * 32 + lane]);
        es.x += (v0.x + v1.x) + (v2.x + v3.x);
        es.y += (v0.y + v1.y) + (v2.y + v3.y);
        es.z += (v0.z + v1.z) + (v2.z + v3.z);
        es.w += (v0.w + v1.w) + (v2.w + v3.w);
    }
    for (; e < end; e++) {
        float4 v = h4_to_f4(Hp[g_esrc[e] * 32 + lane]);
        es.x += v.x; es.y += v.y; es.z += v.z; es.w += v.w;
    }
    float4 h = h4_to_f4(Hp[row * 32 + lane]);
    float4 b = *((const float4*)bias + lane);
    uint2 o;
    *(__half2*)&o.x = __floats2half2_rn(fmaxf((h.x + es.x) * dd + b.x, 0.f),
                                        fmaxf((h.y + es.y) * dd + b.y, 0.f));
    *(__half2*)&o.y = __floats2half2_rn(fmaxf((h.z + es.z) * dd + b.z, 0.f),
                                        fmaxf((h.w + es.w) * dd + b.w, 0.f));
    *((uint2*)OUT + row * 32 + lane) = o;
}

// ---------------- pooling over sorted batch (fp16 in, already ReLU'd) ----------
__global__ void pool_kernel(const __half* __restrict__ X, const int* __restrict__ batch) {
    int c = threadIdx.x;
    int row0 = blockIdx.x * POOL_ROWS;
    if (row0 >= NV) return;
    int rend = min(row0 + POOL_ROWS, NV);
    float acc = 0.f;
    int cur = batch[row0];
    int runstart = row0;
    for (int r = row0; r < rend; r++) {
        int b = batch[r];
        if (b != cur) {
            atomicAdd(&g_summ[cur * HIDDEN + c], acc);
            if (c == 0) atomicAdd(&g_cnt[cur], (float)(r - runstart));
            acc = 0.f; cur = b; runstart = r;
        }
        acc += __half2float(X[(long long)r * HIDDEN + c]);
    }
    atomicAdd(&g_summ[cur * HIDDEN + c], acc);
    if (c == 0) atomicAdd(&g_cnt[cur], (float)(rend - runstart));
}

// ---------------- head: pooled @ W_out + b_out, layernorm; self-cleaning tail --
__global__ void final_kernel(const float* __restrict__ Wo, const float* __restrict__ bo,
                             const float* __restrict__ gamma, const float* __restrict__ beta,
                             float* __restrict__ out) {
    __shared__ float p[HIDDEN];
    __shared__ float rs[DMODEL];
    __shared__ float rq[DMODEL];
    int b = blockIdx.x, c = threadIdx.x;
    if (c < HIDDEN) {
        float cnt = fmaxf(g_cnt[b], 1.f);
        p[c] = g_summ[b * HIDDEN + c] / cnt;
    }
    __syncthreads();
    // self-clean this block's own pooling slots (read above, safe per-block)
    if (c < HIDDEN) g_summ[b * HIDDEN + c] = 0.f;
    if (c == 0) g_cnt[b] = 0.f;

    float y = bo[c];
#pragma unroll 8
    for (int k = 0; k < HIDDEN; k++) y += p[k] * Wo[k * DMODEL + c];
    rs[c] = y;
    rq[c] = y * y;
    __syncthreads();
    for (int s = DMODEL / 2; s > 0; s >>= 1) {
        if (c < s) { rs[c] += rs[c + s]; rq[c] += rq[c + s]; }
        __syncthreads();
    }
    float mu = rs[0] / (float)DMODEL;
    float var = rq[0] / (float)DMODEL - mu * mu;
    out[b * DMODEL + c] = (y - mu) * rsqrtf(var + EPSV) * gamma[c] + beta[c];

    // self-clean the setup state for the next call/replay (not read by this kernel)
    int gtid = b * DMODEL + c;                      // 0 .. 16383
    for (int i = gtid; i < NV; i += BB * DMODEL) g_deg[i] = 0;
    if (gtid < NBLK) g_desc[gtid] = 0ULL;
}

// ---------------- launch ----------------
extern "C" void kernel_launch(void* const* d_in, const int* in_sizes, int n_in,
                              void* d_out, int out_size) {
    const float* vertices = (const float*)d_in[0];
    const int*   eidx     = (const int*)d_in[1];
    const int*   batch    = (const int*)d_in[2];
    const float* W_in     = (const float*)d_in[3];
    const float* b_in     = (const float*)d_in[4];
    const float* W1       = (const float*)d_in[5];
    const float* b1       = (const float*)d_in[6];
    const float* W2       = (const float*)d_in[7];
    const float* b2       = (const float*)d_in[8];
    const float* W3       = (const float*)d_in[9];
    const float* b3       = (const float*)d_in[10];
    const float* W_out    = (const float*)d_in[11];
    const float* b_out    = (const float*)d_in[12];
    const float* gamma    = (const float*)d_in[13];
    const float* beta     = (const float*)d_in[14];
    const int* src = eidx;
    const int* dst = eidx + EE;
    float* out = (float*)d_out;

    __half *ph, *pxa, *pxb;
    __nv_bfloat16* pwh;
    cudaGetSymbolAddress((void**)&ph, g_h16);
    cudaGetSymbolAddress((void**)&pxa, g_x16a);
    cudaGetSymbolAddress((void**)&pxb, g_x16b);
    cudaGetSymbolAddress((void**)&pwh, g_wh);

    cudaFuncSetAttribute((gemm_tc_kernel<true>),
                         cudaFuncAttributeMaxDynamicSharedMemorySize, SMEM_G);
    cudaFuncSetAttribute((gemm_tc_kernel<false>),
                         cudaFuncAttributeMaxDynamicSharedMemorySize, SMEM_G);

    // second stream for capture-safe fork/join overlap (no device memory involved;
    // kernel_launch runs only for correctness + capture, so per-call create is fine)
    cudaStream_t s2;
    cudaStreamCreateWithFlags(&s2, cudaStreamNonBlocking);
    cudaEvent_t ev_fork, ev_scan, ev_g1;
    cudaEventCreateWithFlags(&ev_fork, cudaEventDisableTiming);
    cudaEventCreateWithFlags(&ev_scan, cudaEventDisableTiming);
    cudaEventCreateWithFlags(&ev_g1, cudaEventDisableTiming);

    int gblocks = (NV + 127) / 128;
    int ablocks = (int)(((long long)NV * 32 + 255) / 256);

    // fork s2 from the capture stream
    cudaEventRecord(ev_fork, 0);
    cudaStreamWaitEvent(s2, ev_fork, 0);

    // s2: wsplit (independent)         main: deg -> scan
    wsplit_kernel<<<(3 * HIDDEN * HIDDEN + 255) / 256, 256, 0, s2>>>(W1, W2, W3);
    deg_kernel<<<(EE / 4 + 255) / 256, 256>>>((const int4*)dst);
    scan_kernel<<<NBLK, 256>>>();
    cudaEventRecord(ev_scan, 0);

    // s2: GEMM1 (needs dinv from scan + wsplit)   main: sort (needs scan)
    cudaStreamWaitEvent(s2, ev_scan, 0);
    gemm_tc_kernel<true><<<gblocks, 256, SMEM_G, s2>>>(
        vertices, (const __half*)0, W_in, b_in, pwh + 0 * HIDDEN * HIDDEN, ph);
    cudaEventRecord(ev_g1, s2);
    sort_kernel<<<(EE + 255) / 256, 256>>>(src, dst);

    // join: agg1 needs sort (main) + GEMM1 (s2)
    cudaStreamWaitEvent(0, ev_g1, 0);
    agg_kernel<<<ablocks, 256>>>(ph, b1, pxa);

    // layers 2,3 serial chain on main stream
    gemm_tc_kernel<false><<<gblocks, 256, SMEM_G>>>(
        (const float*)0, pxa, (const float*)0, (const float*)0,
        pwh + 1 * HIDDEN * HIDDEN, ph);
    agg_kernel<<<ablocks, 256>>>(ph, b2, pxb);

    gemm_tc_kernel<false><<<gblocks, 256, SMEM_G>>>(
        (const float*)0, pxb, (const float*)0, (const float*)0,
        pwh + 2 * HIDDEN * HIDDEN, ph);
    agg_kernel<<<ablocks, 256>>>(ph, b3, pxa);

    pool_kernel<<<(NV + POOL_ROWS - 1) / POOL_ROWS, POOL_ROWS>>>(pxa, batch);
    final_kernel<<<BB, DMODEL>>>(W_out, b_out, gamma, beta, out);

    cudaEventDestroy(ev_fork);
    cudaEventDestroy(ev_scan);
    cudaEventDestroy(ev_g1);
    cudaStreamDestroy(s2);
}

// round 15
// speedup vs baseline: 1.3730x; 1.0148x over previous
#include <cuda_runtime.h>
#include <cuda_bf16.h>
#include <cuda_fp16.h>
#include <cstdint>

#define NV 100000
#define EE 1600000
#define BB 64
#define HIDDEN 128
#define DMODEL 256
#define EPSV 1e-5f
#define POOL_ROWS 128
#define NBLK ((NV + 255) / 256)   // 391 scan blocks

// ---------------- scratch (static device globals; no allocation) ----------------
// NOTE: g_deg, g_desc, g_summ, g_cnt rely on the self-cleaning invariant:
// zero at module load, re-zeroed by final_kernel's tail every call.
__device__ __half g_h16[NV * HIDDEN];   // dinv-scaled pre-agg features H' (fp16)
__device__ __half g_x16a[NV * HIDDEN];  // activation ping (fp16)
__device__ __half g_x16b[NV * HIDDEN];  // activation pong (fp16)
__device__ float g_dinv[NV];            // deg^{-1/2}
__device__ int   g_deg[NV];             // in-degree
__device__ int   g_rowptr[NV + 1];      // CSR offsets (by dst)
__device__ int   g_pos[NV];             // running insert positions for sort
__device__ unsigned long long g_desc[NBLK];  // decoupled-lookback descriptors
__device__ int   g_esrc[EE];            // sorted edges: src only (dinv folded into H')
__device__ float g_summ[BB * HIDDEN];   // pooled sums
__device__ float g_cnt[BB];             // pooled counts
__device__ __half g_wf[3][HIDDEN * HIDDEN];  // fp16 W, transposed [n][k]

// ---------------- setup kernels ----------------
__global__ void deg_kernel(const int4* __restrict__ dst4) {
    int e = blockIdx.x * blockDim.x + threadIdx.x;
    if (e < EE / 4) {
        int4 d = dst4[e];
        atomicAdd(&g_deg[d.x], 1);
        atomicAdd(&g_deg[d.y], 1);
        atomicAdd(&g_deg[d.z], 1);
        atomicAdd(&g_deg[d.w], 1);
    }
}

// convert the three layer weights to fp16, transposed [n][k] packed
__global__ void wsplit_kernel(const float* __restrict__ W1,
                              const float* __restrict__ W2,
                              const float* __restrict__ W3) {
    int i = blockIdx.x * blockDim.x + threadIdx.x;   // 0 .. 3*16384-1
    if (i >= 3 * HIDDEN * HIDDEN) return;
    int l = i >> 14, idx = i & 16383;
    const float* W = (l == 0) ? W1 : (l == 1) ? W2 : W3;
    int k = idx >> 7, n = idx & 127;
    g_wf[l][n * HIDDEN + k] = __float2half_rn(W[idx]);
}

// --- single-pass decoupled-lookback exclusive scan of g_deg ---
__global__ void scan_kernel() {
    __shared__ int s[256];
    __shared__ int sh_ex;
    int tid = threadIdx.x;
    int b = blockIdx.x;
    int i = b * 256 + tid;
    int v = (i < NV) ? g_deg[i] : 0;
    s[tid] = v;
    __syncthreads();
#pragma unroll
    for (int off = 1; off < 256; off <<= 1) {
        int t = (tid >= off) ? s[tid - off] : 0;
        __syncthreads();
        s[tid] += t;
        __syncthreads();
    }
    int incl = s[tid];
    int total = s[255];

    if (tid == 0) {
        unsigned long long ex = 0;
        if (b > 0) {
            atomicExch(&g_desc[b], (1ULL << 32) | (unsigned int)total);
            int j = b - 1;
            while (true) {
                unsigned long long d = atomicAdd(&g_desc[j], 0ULL);
                unsigned int st = (unsigned int)(d >> 32);
                if (st == 2u) { ex += (unsigned int)d; break; }
                if (st == 1u) { ex += (unsigned int)d; j--; }
            }
        }
        atomicExch(&g_desc[b], (2ULL << 32) | (unsigned int)(ex + (unsigned int)total));
        sh_ex = (int)ex;
    }
    __syncthreads();
    int excl = sh_ex + incl - v;
    if (i < NV) {
        g_rowptr[i] = excl;
        g_pos[i] = excl;
        g_dinv[i] = rsqrtf((float)v + 1.f);
    }
    if (i == NV - 1) g_rowptr[NV] = excl + v;
}

// counting-sort edges by dst; scalar 1 edge/thread (max warp-level parallelism)
__global__ void sort_kernel(const int* __restrict__ src, const int* __restrict__ dst) {
    int e = blockIdx.x * blockDim.x + threadIdx.x;
    if (e >= EE) return;
    int d = dst[e];
    int p = atomicAdd(&g_pos[d], 1);
    g_esrc[p] = src[e];
}

// ---------------- tensor-core GEMM: H' = dinv * (X @ W)  (fp16 MMA) ------------
__device__ __forceinline__ void mma_fp16(float* c, const uint32_t* a,
                                         uint32_t b0, uint32_t b1) {
    asm volatile(
        "mma.sync.aligned.m16n8k16.row.col.f32.f16.f16.f32 "
        "{%0,%1,%2,%3}, {%4,%5,%6,%7}, {%8,%9}, {%0,%1,%2,%3};\n"
        : "+f"(c[0]), "+f"(c[1]), "+f"(c[2]), "+f"(c[3])
        : "r"(a[0]), "r"(a[1]), "r"(a[2]), "r"(a[3]), "r"(b0), "r"(b1));
}

#define BST 136          // smem row stride in fp16 elements
#define BSTW 68          // same, in 32-bit words
#define XTILE (128 * BST)
#define SMEM_G (2 * XTILE * 2 + 512 * 4)   // Xh + Wh tiles + W_in/b_in floats

template <bool FUSE_IN>
__global__ void gemm_tc_kernel(const float* __restrict__ V,
                               const __half* __restrict__ X16,
                               const float* __restrict__ Wi,
                               const float* __restrict__ bi,
                               const __half* __restrict__ Whg,
                               __half* __restrict__ H) {
    extern __shared__ __half sh[];
    __half* Xh = sh;
    __half* Wh = sh + XTILE;
    float* sWin = (float*)(sh + 2 * XTILE);            // only used when FUSE_IN
    int t = threadIdx.x;
    int row0 = blockIdx.x * 128;

    // fp16 W (packed [n][k]) -> padded smem via float4 copies
#pragma unroll
    for (int i = 0; i < 8; i++) {
        int w4 = i * 256 + t;                // float4 slot 0..2047
        int n = w4 >> 4, kq = w4 & 15;       // 16 float4 per 128-half row
        *(float4*)(Wh + n * BST + kq * 8) = *((const float4*)Whg + w4);
    }
    if (FUSE_IN) {
        for (int i = t; i < 512; i += 256)
            sWin[i] = (i < 384) ? Wi[i] : bi[i - 384];
        __syncthreads();
    }

#pragma unroll
    for (int i = 0; i < 16; i++) {
        int idx = i * 256 + t;
        int r = idx >> 5, q = idx & 31;
        int gr = row0 + r;
        int base = r * BST + q * 4;          // 8-byte aligned
        if (FUSE_IN) {
            float4 v = make_float4(0.f, 0.f, 0.f, 0.f);
            float v0 = 0.f, v1 = 0.f, v2 = 0.f;
            if (gr < NV) {
                v0 = V[gr * 3 + 0]; v1 = V[gr * 3 + 1]; v2 = V[gr * 3 + 2];
            }
            int c = q * 4;
            float* pv = &v.x;
#pragma unroll
            for (int j = 0; j < 4; j++) {
                int cc = c + j;
                pv[j] = sWin[384 + cc] + v0 * sWin[cc] + v1 * sWin[128 + cc]
                        + v2 * sWin[256 + cc];
            }
            *(__half2*)(Xh + base) = __floats2half2_rn(v.x, v.y);
            *(__half2*)(Xh + base + 2) = __floats2half2_rn(v.z, v.w);
        } else {
            uint2 u = make_uint2(0u, 0u);
            if (gr < NV) u = *((const uint2*)X16 + gr * 32 + q);   // exact copy
            *(uint2*)(Xh + base) = u;
        }
    }
    __syncthreads();

    int w = t >> 5, lane = t & 31;
    int wr = w >> 1, wc = w & 1;
    int g = lane >> 2, q4 = lane & 3;

    float acc[2][8][4];
#pragma unroll
    for (int mt = 0; mt < 2; mt++)
#pragma unroll
        for (int nt = 0; nt < 8; nt++)
#pragma unroll
            for (int j = 0; j < 4; j++) acc[mt][nt][j] = 0.f;

    const uint32_t* pXh = (const uint32_t*)Xh;
    const uint32_t* pWh = (const uint32_t*)Wh;

#pragma unroll
    for (int ks = 0; ks < 8; ks++) {
        int kw = ks * 8 + q4;
        uint32_t ah[2][4];
#pragma unroll
        for (int mt = 0; mt < 2; mt++) {
            int r = wr * 32 + mt * 16 + g;
            ah[mt][0] = pXh[r * BSTW + kw];
            ah[mt][1] = pXh[(r + 8) * BSTW + kw];
            ah[mt][2] = pXh[r * BSTW + kw + 4];
            ah[mt][3] = pXh[(r + 8) * BSTW + kw + 4];
        }
#pragma unroll
        for (int nt = 0; nt < 8; nt++) {
            int n = wc * 64 + nt * 8 + g;
            uint32_t bh0 = pWh[n * BSTW + kw];
            uint32_t bh1 = pWh[n * BSTW + kw + 4];
#pragma unroll
            for (int mt = 0; mt < 2; mt++)
                mma_fp16(acc[mt][nt], ah[mt], bh0, bh1);
        }
    }

    // epilogue: scale by dinv[row], store fp16 H'
#pragma unroll
    for (int mt = 0; mt < 2; mt++) {
        int rbase = row0 + wr * 32 + mt * 16 + g;
        float d0 = (rbase < NV) ? g_dinv[rbase] : 0.f;
        float d1 = (rbase + 8 < NV) ? g_dinv[rbase + 8] : 0.f;
#pragma unroll
        for (int nt = 0; nt < 8; nt++) {
            int col = wc * 64 + nt * 8 + q4 * 2;
            if (rbase < NV)
                *(__half2*)(H + rbase * HIDDEN + col) =
                    __floats2half2_rn(acc[mt][nt][0] * d0, acc[mt][nt][1] * d0);
            if (rbase + 8 < NV)
                *(__half2*)(H + (rbase + 8) * HIDDEN + col) =
                    __floats2half2_rn(acc[mt][nt][2] * d1, acc[mt][nt][3] * d1);
        }
    }
}

// ---------------- aggregation: one warp per dst row ---------------------------
__device__ __forceinline__ float4 h4_to_f4(uint2 u) {
    float2 f0 = __half22float2(*(__half2*)&u.x);
    float2 f1 = __half22float2(*(__half2*)&u.y);
    return make_float4(f0.x, f0.y, f1.x, f1.y);
}

// OUT[row] = ReLU( dd * ( H'[row] + sum_e H'[src_e] ) + bias ),  dd = dinv[row]
__global__ void agg_kernel(const __half* __restrict__ H,
                           const float* __restrict__ bias,
                           __half* __restrict__ OUT) {
    int row = (blockIdx.x * blockDim.x + threadIdx.x) >> 5;
    int lane = threadIdx.x & 31;
    if (row >= NV) return;
    int beg = g_rowptr[row], end = g_rowptr[row + 1];
    float dd = g_dinv[row];
    const uint2* Hp = (const uint2*)H;
    float4 es = make_float4(0.f, 0.f, 0.f, 0.f);
    int e = beg;
    for (; e + 3 < end; e += 4) {
        int s0 = g_esrc[e];
        int s1 = g_esrc[e + 1];
        int s2 = g_esrc[e + 2];
        int s3 = g_esrc[e + 3];
        float4 v0 = h4_to_f4(Hp[s0 * 32 + lane]);
        float4 v1 = h4_to_f4(Hp[s1 * 32 + lane]);
        float4 v2 = h4_to_f4(Hp[s2 * 32 + lane]);
        float4 v3 = h4_to_f4(Hp[s3 * 32 + lane]);
        es.x += (v0.x + v1.x) + (v2.x + v3.x);
        es.y += (v0.y + v1.y) + (v2.y + v3.y);
        es.z += (v0.z + v1.z) + (v2.z + v3.z);
        es.w += (v0.w + v1.w) + (v2.w + v3.w);
    }
    for (; e < end; e++) {
        float4 v = h4_to_f4(Hp[g_esrc[e] * 32 + lane]);
        es.x += v.x; es.y += v.y; es.z += v.z; es.w += v.w;
    }
    float4 h = h4_to_f4(Hp[row * 32 + lane]);
    float4 b = *((const float4*)bias + lane);
    uint2 o;
    *(__half2*)&o.x = __floats2half2_rn(fmaxf((h.x + es.x) * dd + b.x, 0.f),
                                        fmaxf((h.y + es.y) * dd + b.y, 0.f));
    *(__half2*)&o.y = __floats2half2_rn(fmaxf((h.z + es.z) * dd + b.z, 0.f),
                                        fmaxf((h.w + es.w) * dd + b.w, 0.f));
    *((uint2*)OUT + row * 32 + lane) = o;
}

// ---------------- pooling over sorted batch (fp16 in, already ReLU'd) ----------
__global__ void pool_kernel(const __half* __restrict__ X, const int* __restrict__ batch) {
    int c = threadIdx.x;
    int row0 = blockIdx.x * POOL_ROWS;
    if (row0 >= NV) return;
    int rend = min(row0 + POOL_ROWS, NV);
    float acc = 0.f;
    int cur = batch[row0];
    int runstart = row0;
    for (int r = row0; r < rend; r++) {
        int b = batch[r];
        if (b != cur) {
            atomicAdd(&g_summ[cur * HIDDEN + c], acc);
            if (c == 0) atomicAdd(&g_cnt[cur], (float)(r - runstart));
            acc = 0.f; cur = b; runstart = r;
        }
        acc += __half2float(X[(long long)r * HIDDEN + c]);
    }
    atomicAdd(&g_summ[cur * HIDDEN + c], acc);
    if (c == 0) atomicAdd(&g_cnt[cur], (float)(rend - runstart));
}

// ---------------- head: pooled @ W_out + b_out, layernorm; self-cleaning tail --
__global__ void final_kernel(const float* __restrict__ Wo, const float* __restrict__ bo,
                             const float* __restrict__ gamma, const float* __restrict__ beta,
                             float* __restrict__ out) {
    __shared__ float p[HIDDEN];
    __shared__ float rs[DMODEL];
    __shared__ float rq[DMODEL];
    int b = blockIdx.x, c = threadIdx.x;
    if (c < HIDDEN) {
        float cnt = fmaxf(g_cnt[b], 1.f);
        p[c] = g_summ[b * HIDDEN + c] / cnt;
    }
    __syncthreads();
    // self-clean this block's own pooling slots (read above, safe per-block)
    if (c < HIDDEN) g_summ[b * HIDDEN + c] = 0.f;
    if (c == 0) g_cnt[b] = 0.f;

    float y = bo[c];
#pragma unroll 8
    for (int k = 0; k < HIDDEN; k++) y += p[k] * Wo[k * DMODEL + c];
    rs[c] = y;
    rq[c] = y * y;
    __syncthreads();
    for (int s = DMODEL / 2; s > 0; s >>= 1) {
        if (c < s) { rs[c] += rs[c + s]; rq[c] += rq[c + s]; }
        __syncthreads();
    }
    float mu = rs[0] / (float)DMODEL;
    float var = rq[0] / (float)DMODEL - mu * mu;
    out[b * DMODEL + c] = (y - mu) * rsqrtf(var + EPSV) * gamma[c] + beta[c];

    // self-clean the setup state for the next call/replay (not read by this kernel)
    int gtid = b * DMODEL + c;                      // 0 .. 16383
    for (int i = gtid; i < NV; i += BB * DMODEL) g_deg[i] = 0;
    if (gtid < NBLK) g_desc[gtid] = 0ULL;
}

// ---------------- launch ----------------
extern "C" void kernel_launch(void* const* d_in, const int* in_sizes, int n_in,
                              void* d_out, int out_size) {
    const float* vertices = (const float*)d_in[0];
    const int*   eidx     = (const int*)d_in[1];
    const int*   batch    = (const int*)d_in[2];
    const float* W_in     = (const float*)d_in[3];
    const float* b_in     = (const float*)d_in[4];
    const float* W1       = (const float*)d_in[5];
    const float* b1       = (const float*)d_in[6];
    const float* W2       = (const float*)d_in[7];
    const float* b2       = (const float*)d_in[8];
    const float* W3       = (const float*)d_in[9];
    const float* b3       = (const float*)d_in[10];
    const float* W_out    = (const float*)d_in[11];
    const float* b_out    = (const float*)d_in[12];
    const float* gamma    = (const float*)d_in[13];
    const float* beta     = (const float*)d_in[14];
    const int* src = eidx;
    const int* dst = eidx + EE;
    float* out = (float*)d_out;

    __half *ph, *pxa, *pxb, *pwf;
    cudaGetSymbolAddress((void**)&ph, g_h16);
    cudaGetSymbolAddress((void**)&pxa, g_x16a);
    cudaGetSymbolAddress((void**)&pxb, g_x16b);
    cudaGetSymbolAddress((void**)&pwf, g_wf);

    cudaFuncSetAttribute((gemm_tc_kernel<true>),
                         cudaFuncAttributeMaxDynamicSharedMemorySize, SMEM_G);
    cudaFuncSetAttribute((gemm_tc_kernel<false>),
                         cudaFuncAttributeMaxDynamicSharedMemorySize, SMEM_G);

    // second stream for capture-safe fork/join overlap (no device memory involved;
    // kernel_launch runs only for correctness + capture, so per-call create is fine)
    cudaStream_t s2;
    cudaStreamCreateWithFlags(&s2, cudaStreamNonBlocking);
    cudaEvent_t ev_fork, ev_scan, ev_g1;
    cudaEventCreateWithFlags(&ev_fork, cudaEventDisableTiming);
    cudaEventCreateWithFlags(&ev_scan, cudaEventDisableTiming);
    cudaEventCreateWithFlags(&ev_g1, cudaEventDisableTiming);

    int gblocks = (NV + 127) / 128;
    int ablocks = (int)(((long long)NV * 32 + 255) / 256);

    // fork s2 from the capture stream
    cudaEventRecord(ev_fork, 0);
    cudaStreamWaitEvent(s2, ev_fork, 0);

    // s2: wsplit (independent)         main: deg -> scan
    wsplit_kernel<<<(3 * HIDDEN * HIDDEN + 255) / 256, 256, 0, s2>>>(W1, W2, W3);
    deg_kernel<<<(EE / 4 + 255) / 256, 256>>>((const int4*)dst);
    scan_kernel<<<NBLK, 256>>>();
    cudaEventRecord(ev_scan, 0);

    // s2: GEMM1 (needs dinv from scan + wsplit)   main: sort (needs scan)
    cudaStreamWaitEvent(s2, ev_scan, 0);
    gemm_tc_kernel<true><<<gblocks, 256, SMEM_G, s2>>>(
        vertices, (const __half*)0, W_in, b_in, pwf + 0 * HIDDEN * HIDDEN, ph);
    cudaEventRecord(ev_g1, s2);
    sort_kernel<<<(EE + 255) / 256, 256>>>(src, dst);

    // join: agg1 needs sort (main) + GEMM1 (s2)
    cudaStreamWaitEvent(0, ev_g1, 0);
    agg_kernel<<<ablocks, 256>>>(ph, b1, pxa);

    // layers 2,3 serial chain on main stream
    gemm_tc_kernel<false><<<gblocks, 256, SMEM_G>>>(
        (const float*)0, pxa, (const float*)0, (const float*)0,
        pwf + 1 * HIDDEN * HIDDEN, ph);
    agg_kernel<<<ablocks, 256>>>(ph, b2, pxb);

    gemm_tc_kernel<false><<<gblocks, 256, SMEM_G>>>(
        (const float*)0, pxb, (const float*)0, (const float*)0,
        pwf + 2 * HIDDEN * HIDDEN, ph);
    agg_kernel<<<ablocks, 256>>>(ph, b3, pxa);

    pool_kernel<<<(NV + POOL_ROWS - 1) / POOL_ROWS, POOL_ROWS>>>(pxa, batch);
    final_kernel<<<BB, DMODEL>>>(W_out, b_out, gamma, beta, out);

    cudaEventDestroy(ev_fork);
    cudaEventDestroy(ev_scan);
    cudaEventDestroy(ev_g1);
    cudaStreamDestroy(s2);
}

// round 17
// speedup vs baseline: 1.4154x; 1.0309x over previous
#include <cuda_runtime.h>
#include <cuda_bf16.h>
#include <cuda_fp16.h>
#include <cstdint>

#define NV 100000
#define EE 1600000
#define BB 64
#define HIDDEN 128
#define DMODEL 256
#define EPSV 1e-5f
#define POOL_ROWS 128
#define NBLK ((NV + 255) / 256)   // 391 scan blocks

// ---------------- scratch (static device globals; no allocation) ----------------
// NOTE: g_deg, g_desc, g_summ, g_cnt rely on the self-cleaning invariant:
// zero at module load, re-zeroed by final_kernel's tail every call.
__device__ __half g_h16[NV * HIDDEN];   // dinv-scaled pre-agg features H' (fp16)
__device__ __half g_x16a[NV * HIDDEN];  // activation ping (fp16)
__device__ __half g_x16b[NV * HIDDEN];  // activation pong (fp16)
__device__ float g_dinv[NV];            // deg^{-1/2}
__device__ int   g_deg[NV];             // in-degree
__device__ int   g_rowptr[NV + 1];      // CSR offsets (by dst)
__device__ int   g_pos[NV];             // running insert positions for sort
__device__ unsigned long long g_desc[NBLK];  // decoupled-lookback descriptors
__device__ int   g_esrc[EE];            // sorted edges: src only (dinv folded into H')
__device__ float g_summ[BB * HIDDEN];   // pooled sums
__device__ float g_cnt[BB];             // pooled counts
__device__ __half g_wf[3][HIDDEN * HIDDEN];  // fp16 W, transposed [n][k]

// ---------------- setup kernels ----------------
__global__ void deg_kernel(const int4* __restrict__ dst4) {
    int e = blockIdx.x * blockDim.x + threadIdx.x;
    if (e < EE / 4) {
        int4 d = dst4[e];
        atomicAdd(&g_deg[d.x], 1);
        atomicAdd(&g_deg[d.y], 1);
        atomicAdd(&g_deg[d.z], 1);
        atomicAdd(&g_deg[d.w], 1);
    }
}

// dinv from deg only (lets GEMM1 start without waiting for the scan)
__global__ void dinv_kernel() {
    int i = blockIdx.x * blockDim.x + threadIdx.x;
    if (i < NV) g_dinv[i] = rsqrtf((float)g_deg[i] + 1.f);
}

// convert the three layer weights to fp16, transposed [n][k] packed
__global__ void wsplit_kernel(const float* __restrict__ W1,
                              const float* __restrict__ W2,
                              const float* __restrict__ W3) {
    int i = blockIdx.x * blockDim.x + threadIdx.x;   // 0 .. 3*16384-1
    if (i >= 3 * HIDDEN * HIDDEN) return;
    int l = i >> 14, idx = i & 16383;
    const float* W = (l == 0) ? W1 : (l == 1) ? W2 : W3;
    int k = idx >> 7, n = idx & 127;
    g_wf[l][n * HIDDEN + k] = __float2half_rn(W[idx]);
}

// --- single-pass decoupled-lookback exclusive scan of g_deg ---
__global__ void scan_kernel() {
    __shared__ int s[256];
    __shared__ int sh_ex;
    int tid = threadIdx.x;
    int b = blockIdx.x;
    int i = b * 256 + tid;
    int v = (i < NV) ? g_deg[i] : 0;
    s[tid] = v;
    __syncthreads();
#pragma unroll
    for (int off = 1; off < 256; off <<= 1) {
        int t = (tid >= off) ? s[tid - off] : 0;
        __syncthreads();
        s[tid] += t;
        __syncthreads();
    }
    int incl = s[tid];
    int total = s[255];

    if (tid == 0) {
        unsigned long long ex = 0;
        if (b > 0) {
            atomicExch(&g_desc[b], (1ULL << 32) | (unsigned int)total);
            int j = b - 1;
            while (true) {
                unsigned long long d = atomicAdd(&g_desc[j], 0ULL);
                unsigned int st = (unsigned int)(d >> 32);
                if (st == 2u) { ex += (unsigned int)d; break; }
                if (st == 1u) { ex += (unsigned int)d; j--; }
            }
        }
        atomicExch(&g_desc[b], (2ULL << 32) | (unsigned int)(ex + (unsigned int)total));
        sh_ex = (int)ex;
    }
    __syncthreads();
    int excl = sh_ex + incl - v;
    if (i < NV) {
        g_rowptr[i] = excl;
        g_pos[i] = excl;
    }
    if (i == NV - 1) g_rowptr[NV] = excl + v;
}

// counting-sort edges by dst; scalar 1 edge/thread (max warp-level parallelism)
__global__ void sort_kernel(const int* __restrict__ src, const int* __restrict__ dst) {
    int e = blockIdx.x * blockDim.x + threadIdx.x;
    if (e >= EE) return;
    int d = dst[e];
    int p = atomicAdd(&g_pos[d], 1);
    g_esrc[p] = src[e];
}

// ---------------- tensor-core GEMM: H' = dinv * (X @ W)  (fp16 MMA) ------------
__device__ __forceinline__ void mma_fp16(float* c, const uint32_t* a,
                                         uint32_t b0, uint32_t b1) {
    asm volatile(
        "mma.sync.aligned.m16n8k16.row.col.f32.f16.f16.f32 "
        "{%0,%1,%2,%3}, {%4,%5,%6,%7}, {%8,%9}, {%0,%1,%2,%3};\n"
        : "+f"(c[0]), "+f"(c[1]), "+f"(c[2]), "+f"(c[3])
        : "r"(a[0]), "r"(a[1]), "r"(a[2]), "r"(a[3]), "r"(b0), "r"(b1));
}

#define BST 136          // smem row stride in fp16 elements
#define BSTW 68          // same, in 32-bit words
#define XTILE (128 * BST)
#define SMEM_G (2 * XTILE * 2 + 512 * 4)   // Xh + Wh tiles + W_in/b_in floats

template <bool FUSE_IN>
__global__ void __launch_bounds__(256, 2)
gemm_tc_kernel(const float* __restrict__ V,
               const __half* __restrict__ X16,
               const float* __restrict__ Wi,
               const float* __restrict__ bi,
               const __half* __restrict__ Whg,
               __half* __restrict__ H) {
    extern __shared__ __half sh[];
    __half* Xh = sh;
    __half* Wh = sh + XTILE;
    float* sWin = (float*)(sh + 2 * XTILE);            // only used when FUSE_IN
    int t = threadIdx.x;
    int row0 = blockIdx.x * 128;

    // fp16 W (packed [n][k]) -> padded smem via float4 copies
#pragma unroll
    for (int i = 0; i < 8; i++) {
        int w4 = i * 256 + t;                // float4 slot 0..2047
        int n = w4 >> 4, kq = w4 & 15;       // 16 float4 per 128-half row
        *(float4*)(Wh + n * BST + kq * 8) = *((const float4*)Whg + w4);
    }
    if (FUSE_IN) {
        for (int i = t; i < 512; i += 256)
            sWin[i] = (i < 384) ? Wi[i] : bi[i - 384];
        __syncthreads();
    }

#pragma unroll
    for (int i = 0; i < 16; i++) {
        int idx = i * 256 + t;
        int r = idx >> 5, q = idx & 31;
        int gr = row0 + r;
        int base = r * BST + q * 4;          // 8-byte aligned
        if (FUSE_IN) {
            float4 v = make_float4(0.f, 0.f, 0.f, 0.f);
            float v0 = 0.f, v1 = 0.f, v2 = 0.f;
            if (gr < NV) {
                v0 = V[gr * 3 + 0]; v1 = V[gr * 3 + 1]; v2 = V[gr * 3 + 2];
            }
            int c = q * 4;
            float* pv = &v.x;
#pragma unroll
            for (int j = 0; j < 4; j++) {
                int cc = c + j;
                pv[j] = sWin[384 + cc] + v0 * sWin[cc] + v1 * sWin[128 + cc]
                        + v2 * sWin[256 + cc];
            }
            *(__half2*)(Xh + base) = __floats2half2_rn(v.x, v.y);
            *(__half2*)(Xh + base + 2) = __floats2half2_rn(v.z, v.w);
        } else {
            uint2 u = make_uint2(0u, 0u);
            if (gr < NV) u = *((const uint2*)X16 + gr * 32 + q);   // exact copy
            *(uint2*)(Xh + base) = u;
        }
    }
    __syncthreads();

    int w = t >> 5, lane = t & 31;
    int wr = w >> 1, wc = w & 1;
    int g = lane >> 2, q4 = lane & 3;

    float acc[2][8][4];
#pragma unroll
    for (int mt = 0; mt < 2; mt++)
#pragma unroll
        for (int nt = 0; nt < 8; nt++)
#pragma unroll
            for (int j = 0; j < 4; j++) acc[mt][nt][j] = 0.f;

    const uint32_t* pXh = (const uint32_t*)Xh;
    const uint32_t* pWh = (const uint32_t*)Wh;

    // software-pipelined mainloop: prefetch next k-step's A fragments
    uint32_t ah[2][4];
#pragma unroll
    for (int mt = 0; mt < 2; mt++) {
        int r = wr * 32 + mt * 16 + g;
        ah[mt][0] = pXh[r * BSTW + q4];
        ah[mt][1] = pXh[(r + 8) * BSTW + q4];
        ah[mt][2] = pXh[r * BSTW + q4 + 4];
        ah[mt][3] = pXh[(r + 8) * BSTW + q4 + 4];
    }
#pragma unroll
    for (int ks = 0; ks < 8; ks++) {
        int kw = ks * 8 + q4;
        uint32_t ahn[2][4];
        if (ks < 7) {
            int kwn = kw + 8;
#pragma unroll
            for (int mt = 0; mt < 2; mt++) {
                int r = wr * 32 + mt * 16 + g;
                ahn[mt][0] = pXh[r * BSTW + kwn];
                ahn[mt][1] = pXh[(r + 8) * BSTW + kwn];
                ahn[mt][2] = pXh[r * BSTW + kwn + 4];
                ahn[mt][3] = pXh[(r + 8) * BSTW + kwn + 4];
            }
        }
#pragma unroll
        for (int nt = 0; nt < 8; nt++) {
            int n = wc * 64 + nt * 8 + g;
            uint32_t bh0 = pWh[n * BSTW + kw];
            uint32_t bh1 = pWh[n * BSTW + kw + 4];
#pragma unroll
            for (int mt = 0; mt < 2; mt++)
                mma_fp16(acc[mt][nt], ah[mt], bh0, bh1);
        }
        if (ks < 7) {
#pragma unroll
            for (int mt = 0; mt < 2; mt++)
#pragma unroll
                for (int j = 0; j < 4; j++) ah[mt][j] = ahn[mt][j];
        }
    }

    // epilogue: scale by dinv[row], store fp16 H'
#pragma unroll
    for (int mt = 0; mt < 2; mt++) {
        int rbase = row0 + wr * 32 + mt * 16 + g;
        float d0 = (rbase < NV) ? g_dinv[rbase] : 0.f;
        float d1 = (rbase + 8 < NV) ? g_dinv[rbase + 8] : 0.f;
#pragma unroll
        for (int nt = 0; nt < 8; nt++) {
            int col = wc * 64 + nt * 8 + q4 * 2;
            if (rbase < NV)
                *(__half2*)(H + rbase * HIDDEN + col) =
                    __floats2half2_rn(acc[mt][nt][0] * d0, acc[mt][nt][1] * d0);
            if (rbase + 8 < NV)
                *(__half2*)(H + (rbase + 8) * HIDDEN + col) =
                    __floats2half2_rn(acc[mt][nt][2] * d1, acc[mt][nt][3] * d1);
        }
    }
}

// ---------------- aggregation: one warp per dst row ---------------------------
__device__ __forceinline__ float4 h4_to_f4(uint2 u) {
    float2 f0 = __half22float2(*(__half2*)&u.x);
    float2 f1 = __half22float2(*(__half2*)&u.y);
    return make_float4(f0.x, f0.y, f1.x, f1.y);
}

// OUT[row] = ReLU( dd * ( H'[row] + sum_e H'[src_e] ) + bias ),  dd = dinv[row]
__global__ void agg_kernel(const __half* __restrict__ H,
                           const float* __restrict__ bias,
                           __half* __restrict__ OUT) {
    int row = (blockIdx.x * blockDim.x + threadIdx.x) >> 5;
    int lane = threadIdx.x & 31;
    if (row >= NV) return;
    int beg = g_rowptr[row], end = g_rowptr[row + 1];
    float dd = g_dinv[row];
    const uint2* Hp = (const uint2*)H;
    float4 es = make_float4(0.f, 0.f, 0.f, 0.f);
    int e = beg;
    for (; e + 3 < end; e += 4) {
        int s0 = g_esrc[e];
        int s1 = g_esrc[e + 1];
        int s2 = g_esrc[e + 2];
        int s3 = g_esrc[e + 3];
        float4 v0 = h4_to_f4(Hp[s0 * 32 + lane]);
        float4 v1 = h4_to_f4(Hp[s1 * 32 + lane]);
        float4 v2 = h4_to_f4(Hp[s2 * 32 + lane]);
        float4 v3 = h4_to_f4(Hp[s3 * 32 + lane]);
        es.x += (v0.x + v1.x) + (v2.x + v3.x);
        es.y += (v0.y + v1.y) + (v2.y + v3.y);
        es.z += (v0.z + v1.z) + (v2.z + v3.z);
        es.w += (v0.w + v1.w) + (v2.w + v3.w);
    }
    for (; e < end; e++) {
        float4 v = h4_to_f4(Hp[g_esrc[e] * 32 + lane]);
        es.x += v.x; es.y += v.y; es.z += v.z; es.w += v.w;
    }
    float4 h = h4_to_f4(Hp[row * 32 + lane]);
    float4 b = *((const float4*)bias + lane);
    uint2 o;
    *(__half2*)&o.x = __floats2half2_rn(fmaxf((h.x + es.x) * dd + b.x, 0.f),
                                        fmaxf((h.y + es.y) * dd + b.y, 0.f));
    *(__half2*)&o.y = __floats2half2_rn(fmaxf((h.z + es.z) * dd + b.z, 0.f),
                                        fmaxf((h.w + es.w) * dd + b.w, 0.f));
    *((uint2*)OUT + row * 32 + lane) = o;
}

// ---------------- pooling over sorted batch (fp16 in, already ReLU'd) ----------
__global__ void pool_kernel(const __half* __restrict__ X, const int* __restrict__ batch) {
    int c = threadIdx.x;
    int row0 = blockIdx.x * POOL_ROWS;
    if (row0 >= NV) return;
    int rend = min(row0 + POOL_ROWS, NV);
    float acc = 0.f;
    int cur = batch[row0];
    int runstart = row0;
    for (int r = row0; r < rend; r++) {
        int b = batch[r];
        if (b != cur) {
            atomicAdd(&g_summ[cur * HIDDEN + c], acc);
            if (c == 0) atomicAdd(&g_cnt[cur], (float)(r - runstart));
            acc = 0.f; cur = b; runstart = r;
        }
        acc += __half2float(X[(long long)r * HIDDEN + c]);
    }
    atomicAdd(&g_summ[cur * HIDDEN + c], acc);
    if (c == 0) atomicAdd(&g_cnt[cur], (float)(rend - runstart));
}

// ---------------- head: pooled @ W_out + b_out, layernorm; self-cleaning tail --
__global__ void final_kernel(const float* __restrict__ Wo, const float* __restrict__ bo,
                             const float* __restrict__ gamma, const float* __restrict__ beta,
                             float* __restrict__ out) {
    __shared__ float p[HIDDEN];
    __shared__ float rs[DMODEL];
    __shared__ float rq[DMODEL];
    int b = blockIdx.x, c = threadIdx.x;
    if (c < HIDDEN) {
        float cnt = fmaxf(g_cnt[b], 1.f);
        p[c] = g_summ[b * HIDDEN + c] / cnt;
    }
    __syncthreads();
    // self-clean this block's own pooling slots (read above, safe per-block)
    if (c < HIDDEN) g_summ[b * HIDDEN + c] = 0.f;
    if (c == 0) g_cnt[b] = 0.f;

    float y = bo[c];
#pragma unroll 8
    for (int k = 0; k < HIDDEN; k++) y += p[k] * Wo[k * DMODEL + c];
    rs[c] = y;
    rq[c] = y * y;
    __syncthreads();
    for (int s = DMODEL / 2; s > 0; s >>= 1) {
        if (c < s) { rs[c] += rs[c + s]; rq[c] += rq[c + s]; }
        __syncthreads();
    }
    float mu = rs[0] / (float)DMODEL;
    float var = rq[0] / (float)DMODEL - mu * mu;
    out[b * DMODEL + c] = (y - mu) * rsqrtf(var + EPSV) * gamma[c] + beta[c];

    // self-clean the setup state for the next call/replay (not read by this kernel)
    int gtid = b * DMODEL + c;                      // 0 .. 16383
    for (int i = gtid; i < NV; i += BB * DMODEL) g_deg[i] = 0;
    if (gtid < NBLK) g_desc[gtid] = 0ULL;
}

// ---------------- launch ----------------
extern "C" void kernel_launch(void* const* d_in, const int* in_sizes, int n_in,
                              void* d_out, int out_size) {
    const float* vertices = (const float*)d_in[0];
    const int*   eidx     = (const int*)d_in[1];
    const int*   batch    = (const int*)d_in[2];
    const float* W_in     = (const float*)d_in[3];
    const float* b_in     = (const float*)d_in[4];
    const float* W1       = (const float*)d_in[5];
    const float* b1       = (const float*)d_in[6];
    const float* W2       = (const float*)d_in[7];
    const float* b2       = (const float*)d_in[8];
    const float* W3       = (const float*)d_in[9];
    const float* b3       = (const float*)d_in[10];
    const float* W_out    = (const float*)d_in[11];
    const float* b_out    = (const float*)d_in[12];
    const float* gamma    = (const float*)d_in[13];
    const float* beta     = (const float*)d_in[14];
    const int* src = eidx;
    const int* dst = eidx + EE;
    float* out = (float*)d_out;

    __half *ph, *pxa, *pxb, *pwf;
    cudaGetSymbolAddress((void**)&ph, g_h16);
    cudaGetSymbolAddress((void**)&pxa, g_x16a);
    cudaGetSymbolAddress((void**)&pxb, g_x16b);
    cudaGetSymbolAddress((void**)&pwf, g_wf);

    cudaFuncSetAttribute((gemm_tc_kernel<true>),
                         cudaFuncAttributeMaxDynamicSharedMemorySize, SMEM_G);
    cudaFuncSetAttribute((gemm_tc_kernel<false>),
                         cudaFuncAttributeMaxDynamicSharedMemorySize, SMEM_G);

    // second stream for capture-safe fork/join overlap
    cudaStream_t s2;
    cudaStreamCreateWithFlags(&s2, cudaStreamNonBlocking);
    cudaEvent_t ev_fork, ev_deg, ev_g1;
    cudaEventCreateWithFlags(&ev_fork, cudaEventDisableTiming);
    cudaEventCreateWithFlags(&ev_deg, cudaEventDisableTiming);
    cudaEventCreateWithFlags(&ev_g1, cudaEventDisableTiming);

    int gblocks = (NV + 127) / 128;
    int ablocks = (int)(((long long)NV * 32 + 255) / 256);
    int nb256 = (NV + 255) / 256;

    // fork s2 from the capture stream
    cudaEventRecord(ev_fork, 0);
    cudaStreamWaitEvent(s2, ev_fork, 0);

    // s2: wsplit (independent)         main: deg
    wsplit_kernel<<<(3 * HIDDEN * HIDDEN + 255) / 256, 256, 0, s2>>>(W1, W2, W3);
    deg_kernel<<<(EE / 4 + 255) / 256, 256>>>((const int4*)dst);
    cudaEventRecord(ev_deg, 0);

    // s2: dinv -> GEMM1 (needs only deg)   main: scan -> sort
    cudaStreamWaitEvent(s2, ev_deg, 0);
    dinv_kernel<<<nb256, 256, 0, s2>>>();
    gemm_tc_kernel<true><<<gblocks, 256, SMEM_G, s2>>>(
        vertices, (const __half*)0, W_in, b_in, pwf + 0 * HIDDEN * HIDDEN, ph);
    cudaEventRecord(ev_g1, s2);
    scan_kernel<<<NBLK, 256>>>();
    sort_kernel<<<(EE + 255) / 256, 256>>>(src, dst);

    // join: agg1 needs sort (main) + GEMM1 (s2)
    cudaStreamWaitEvent(0, ev_g1, 0);
    agg_kernel<<<ablocks, 256>>>(ph, b1, pxa);

    // layers 2,3 serial chain on main stream
    gemm_tc_kernel<false><<<gblocks, 256, SMEM_G>>>(
        (const float*)0, pxa, (const float*)0, (const float*)0,
        pwf + 1 * HIDDEN * HIDDEN, ph);
    agg_kernel<<<ablocks, 256>>>(ph, b2, pxb);

    gemm_tc_kernel<false><<<gblocks, 256, SMEM_G>>>(
        (const float*)0, pxb, (const float*)0, (const float*)0,
        pwf + 2 * HIDDEN * HIDDEN, ph);
    agg_kernel<<<ablocks, 256>>>(ph, b3, pxa);

    pool_kernel<<<(NV + POOL_ROWS - 1) / POOL_ROWS, POOL_ROWS>>>(pxa, batch);
    final_kernel<<<BB, DMODEL>>>(W_out, b_out, gamma, beta, out);

    cudaEventDestroy(ev_fork);
    cudaEventDestroy(ev_deg);
    cudaEventDestroy(ev_g1);
    cudaStreamDestroy(s2);
}